// round 3
// baseline (speedup 1.0000x reference)
#include <cuda_runtime.h>
#include <cuda_fp16.h>
#include <cstdint>

#define TOK    8192
#define HID    3072
#define INTERC 8192
#define KT     64
#define NK1    (HID / KT)
#define NK2    (INTERC / KT)

#define AG_OFF 1024u
#define AU_OFF (AG_OFF + 2u * 16384u)
#define B1_OFF (AU_OFF + 2u * 16384u)
#define SMEM1  (B1_OFF + 2u * 32768u)

#define A2_OFF 1024u
#define B2_OFF (A2_OFF + 2u * 16384u)
#define SMEM2  (B2_OFF + 2u * 32768u)

// kind::f16, a/b = F16, dtype = F32, M=128, N=256
#define IDESC_MMA ((1u << 4) | (32u << 17) | (8u << 24))

// tcgen05 is only legal in the arch-specific (sm_103a / sm_100a) passes.
#if !defined(__CUDA_ARCH__) || defined(__CUDA_ARCH_FEAT_SM103_ALL) || defined(__CUDA_ARCH_FEAT_SM100_ALL) || defined(__CUDA_ARCH_FEAT_SM101_ALL)
#define HAS_TCGEN05 1
#else
#define HAS_TCGEN05 0
#endif

__device__ __align__(1024) __half g_xh [(size_t)TOK * HID];
__device__ __align__(1024) __half g_w1h[(size_t)(2 * INTERC) * HID];
__device__ __align__(1024) __half g_w2h[(size_t)HID * INTERC];
__device__ __align__(1024) __half g_hid[(size_t)TOK * INTERC];

__device__ __forceinline__ uint32_t smem_u32(const void* p) {
    uint32_t a;
    asm("{ .reg .u64 t; cvta.to.shared.u64 t, %1; cvt.u32.u64 %0, t; }" : "=r"(a) : "l"(p));
    return a;
}
#define SWZ(o) ((o) ^ (((o) >> 3) & 0x70))

__device__ __forceinline__ uint64_t make_desc(uint32_t addr) {
    const uint64_t base = (uint64_t(2) << 61) | (uint64_t(1) << 46) |
                          (uint64_t(64) << 32) | (uint64_t(1) << 16);
    return base | ((uint64_t)(addr >> 4) & 0x3FFF);
}
__device__ __forceinline__ void cpa16(uint32_t dst, const void* src) {
    asm volatile("cp.async.cg.shared.global [%0], [%1], 16;" :: "r"(dst), "l"(src));
}

#if HAS_TCGEN05
__device__ __forceinline__ void mma_f16_ss(uint32_t d, uint64_t a, uint64_t b, uint32_t en) {
    asm volatile("{\n\t.reg .pred p;\n\tsetp.ne.u32 p, %4, 0;\n\t"
        "tcgen05.mma.cta_group::1.kind::f16 [%0], %1, %2, %3, {%5, %5, %5, %5}, p;\n\t}"
        :: "r"(d), "l"(a), "l"(b), "r"(IDESC_MMA), "r"(en), "r"(0u) : "memory");
}
#define TCG_ALLOC(sa, n)  asm volatile("tcgen05.alloc.cta_group::1.sync.aligned.shared::cta.b32 [%0], %1;" :: "r"(sa), "r"((uint32_t)(n)) : "memory")
#define TCG_DEALLOC(t, n) asm volatile("tcgen05.dealloc.cta_group::1.sync.aligned.b32 %0, %1;" :: "r"(t), "r"((uint32_t)(n)))
#define TCG_RELQ()        asm volatile("tcgen05.relinquish_alloc_permit.cta_group::1.sync.aligned;")
#define TCG_COMMIT(a)     asm volatile("tcgen05.commit.cta_group::1.mbarrier::arrive::one.shared::cluster.b64 [%0];" :: "r"(a) : "memory")
#define TCG_FENCE_AFTER() asm volatile("tcgen05.fence::after_thread_sync;" ::: "memory")
#define TCG_WAIT_LD()     asm volatile("tcgen05.wait::ld.sync.aligned;" ::: "memory")

#define LDTM_X32(r, a)                                                            \
    asm volatile("tcgen05.ld.sync.aligned.32x32b.x32.b32 "                        \
        "{%0, %1, %2, %3, %4, %5, %6, %7, %8, %9, %10, %11, %12, %13, %14, %15, " \
        " %16, %17, %18, %19, %20, %21, %22, %23, %24, %25, %26, %27, %28, %29, %30, %31}, [%32];" \
        : "=r"((r)[0]),  "=r"((r)[1]),  "=r"((r)[2]),  "=r"((r)[3]),              \
          "=r"((r)[4]),  "=r"((r)[5]),  "=r"((r)[6]),  "=r"((r)[7]),              \
          "=r"((r)[8]),  "=r"((r)[9]),  "=r"((r)[10]), "=r"((r)[11]),             \
          "=r"((r)[12]), "=r"((r)[13]), "=r"((r)[14]), "=r"((r)[15]),             \
          "=r"((r)[16]), "=r"((r)[17]), "=r"((r)[18]), "=r"((r)[19]),             \
          "=r"((r)[20]), "=r"((r)[21]), "=r"((r)[22]), "=r"((r)[23]),             \
          "=r"((r)[24]), "=r"((r)[25]), "=r"((r)[26]), "=r"((r)[27]),             \
          "=r"((r)[28]), "=r"((r)[29]), "=r"((r)[30]), "=r"((r)[31])              \
        : "r"(a))
#endif // HAS_TCGEN05

#define MBAR_INIT(a, c)   asm volatile("mbarrier.init.shared.b64 [%0], %1;" :: "r"(a), "r"((uint32_t)(c)) : "memory")
#define MBAR_WAIT(addr, ph) do {                                                 \
    uint32_t _d;                                                                 \
    asm volatile("{\n\t.reg .pred p;\n\t"                                        \
        "mbarrier.try_wait.parity.acquire.cta.shared::cta.b64 p, [%1], %2;\n\t"  \
        "selp.b32 %0, 1, 0, p;\n\t}" : "=r"(_d) : "r"(addr), "r"(ph) : "memory");\
    while (!_d)                                                                  \
        asm volatile("{\n\t.reg .pred p;\n\t"                                    \
            "mbarrier.try_wait.parity.acquire.cta.shared::cta.b64 p, [%1], %2, 0x989680;\n\t" \
            "selp.b32 %0, 1, 0, p;\n\t}" : "=r"(_d) : "r"(addr), "r"(ph) : "memory"); \
} while (0)

// rows x 64-half K-major tile -> SW128 smem, 256 threads, rows % 32 == 0
__device__ __forceinline__ void load_tile(uint32_t sdst, const __half* g,
                                          int ldk, int rows, int tid) {
    const int nit = rows / 32;
#pragma unroll
    for (int i = 0; i < nit; i++) {
        int idx = tid + i * 256;
        int r = idx >> 3, c = idx & 7;
        uint32_t off = (uint32_t)(r * 128 + c * 16);
        cpa16(sdst + SWZ(off), (const void*)(g + (size_t)r * ldk + c * 8));
    }
}

__global__ void __launch_bounds__(256) cvt_f32_k(const float4* __restrict__ s,
                                                 uint2* __restrict__ d, int n4) {
    int i = blockIdx.x * 256 + threadIdx.x;
    if (i >= n4) return;
    float4 v = s[i];
    __half2 a = __floats2half2_rn(v.x, v.y), b = __floats2half2_rn(v.z, v.w);
    d[i] = make_uint2(*(uint32_t*)&a, *(uint32_t*)&b);
}
__global__ void __launch_bounds__(256) cvt_i32_k(const int4* __restrict__ s,
                                                 uint2* __restrict__ d, int n4) {
    int i = blockIdx.x * 256 + threadIdx.x;
    if (i >= n4) return;
    int4 v = s[i];
    __half2 a = __floats2half2_rn((float)v.x, (float)v.y),
            b = __floats2half2_rn((float)v.z, (float)v.w);
    d[i] = make_uint2(*(uint32_t*)&a, *(uint32_t*)&b);
}

// ---------------- GEMM1: gate/up + SiLU -> g_hid (pre-scaled 1/16) -------------
__global__ void __launch_bounds__(256, 1) ffn_gemm1(const float* __restrict__ gus) {
#if HAS_TCGEN05
    extern __shared__ char smem[];
    uint32_t sb = smem_u32(smem);
    const int tid = threadIdx.x, wid = tid >> 5, lid = tid & 31;
    const int t0 = blockIdx.x * 256, g0 = blockIdx.y * 128;

    if (wid == 0) TCG_ALLOC(sb, 512);
    if (tid == 0) { MBAR_INIT(sb + 8, 1); MBAR_INIT(sb + 16, 1); }
    __syncthreads();
    uint32_t tb;
    asm volatile("ld.shared.b32 %0, [%1];" : "=r"(tb) : "r"(sb));

    const __half* Ag = g_w1h + (size_t)g0 * HID;
    const __half* Au = g_w1h + (size_t)(INTERC + g0) * HID;
    const __half* Bx = g_xh + (size_t)t0 * HID;

    load_tile(sb + AG_OFF, Ag, HID, 128, tid);
    load_tile(sb + AU_OFF, Au, HID, 128, tid);
    load_tile(sb + B1_OFF, Bx, HID, 256, tid);
    asm volatile("cp.async.commit_group;" ::: "memory");

    for (int kc = 0; kc < NK1; kc++) {
        const uint32_t cur = (uint32_t)(kc & 1);
        if (kc + 1 < NK1) {
            if (kc >= 1) MBAR_WAIT(sb + 8 + (((uint32_t)(kc - 1) & 1u) << 3),
                                   (uint32_t)(((kc - 1) >> 1) & 1));
            const uint32_t nb = cur ^ 1u;
            load_tile(sb + AG_OFF + nb * 16384u, Ag + (kc + 1) * KT, HID, 128, tid);
            load_tile(sb + AU_OFF + nb * 16384u, Au + (kc + 1) * KT, HID, 128, tid);
            load_tile(sb + B1_OFF + nb * 32768u, Bx + (kc + 1) * KT, HID, 256, tid);
            asm volatile("cp.async.commit_group;" ::: "memory");
            asm volatile("cp.async.wait_group 1;" ::: "memory");
        } else {
            asm volatile("cp.async.wait_group 0;" ::: "memory");
        }
        asm volatile("fence.proxy.async.shared::cta;" ::: "memory");
        __syncthreads();
        if (tid == 0) {
            uint64_t ad = make_desc(sb + AG_OFF + cur * 16384u);
            uint64_t au = make_desc(sb + AU_OFF + cur * 16384u);
            uint64_t bd = make_desc(sb + B1_OFF + cur * 32768u);
#pragma unroll
            for (int ks = 0; ks < 4; ks++) {
                uint32_t en = (kc | ks) ? 1u : 0u;
                mma_f16_ss(tb,        ad + ks * 2, bd + ks * 2, en);
                mma_f16_ss(tb + 256u, au + ks * 2, bd + ks * 2, en);
            }
            TCG_COMMIT(sb + 8 + (cur << 3));
        }
    }
    MBAR_WAIT(sb + 8 + (((uint32_t)(NK1 - 1) & 1u) << 3), (uint32_t)(((NK1 - 1) >> 1) & 1));
    TCG_FENCE_AFTER();

    const int wg = wid >> 2;
    const int o = g0 + ((wid & 3) << 5) + lid;
    const float sg = gus[o], su = gus[INTERC + o];
#pragma unroll
    for (int cc = 0; cc < 4; cc++) {
        const int cb = wg * 128 + cc * 32;
        uint32_t gr[32], ur[32];
        LDTM_X32(gr, tb + (uint32_t)cb);
        LDTM_X32(ur, tb + 256u + (uint32_t)cb);
        TCG_WAIT_LD();
#pragma unroll
        for (int j = 0; j < 32; j++) {
            float g = __uint_as_float(gr[j]) * sg;
            float u = __uint_as_float(ur[j]) * su;
            float h = g * u * 0.0625f / (1.0f + __expf(-g));
            g_hid[(size_t)(t0 + cb + j) * INTERC + o] = __float2half_rn(h);
        }
    }
    __syncthreads();
    if (wid == 0) { TCG_RELQ(); TCG_DEALLOC(tb, 512); }
#endif // HAS_TCGEN05
}

// ---------------- GEMM2: down proj -> out f32 ---------------------------------
__global__ void __launch_bounds__(256, 1) ffn_gemm2(const float* __restrict__ dsc,
                                                    float* __restrict__ out) {
#if HAS_TCGEN05
    extern __shared__ char smem[];
    uint32_t sb = smem_u32(smem);
    const int tid = threadIdx.x, wid = tid >> 5, lid = tid & 31;
    const int t0 = blockIdx.x * 256, n0 = blockIdx.y * 128;

    if (wid == 0) TCG_ALLOC(sb, 256);
    if (tid == 0) { MBAR_INIT(sb + 8, 1); MBAR_INIT(sb + 16, 1); }
    __syncthreads();
    uint32_t tb;
    asm volatile("ld.shared.b32 %0, [%1];" : "=r"(tb) : "r"(sb));

    const __half* A = g_w2h + (size_t)n0 * INTERC;
    const __half* B = g_hid + (size_t)t0 * INTERC;

    load_tile(sb + A2_OFF, A, INTERC, 128, tid);
    load_tile(sb + B2_OFF, B, INTERC, 256, tid);
    asm volatile("cp.async.commit_group;" ::: "memory");

    for (int kc = 0; kc < NK2; kc++) {
        const uint32_t cur = (uint32_t)(kc & 1);
        if (kc + 1 < NK2) {
            if (kc >= 1) MBAR_WAIT(sb + 8 + (((uint32_t)(kc - 1) & 1u) << 3),
                                   (uint32_t)(((kc - 1) >> 1) & 1));
            const uint32_t nb = cur ^ 1u;
            load_tile(sb + A2_OFF + nb * 16384u, A + (kc + 1) * KT, INTERC, 128, tid);
            load_tile(sb + B2_OFF + nb * 32768u, B + (kc + 1) * KT, INTERC, 256, tid);
            asm volatile("cp.async.commit_group;" ::: "memory");
            asm volatile("cp.async.wait_group 1;" ::: "memory");
        } else {
            asm volatile("cp.async.wait_group 0;" ::: "memory");
        }
        asm volatile("fence.proxy.async.shared::cta;" ::: "memory");
        __syncthreads();
        if (tid == 0) {
            uint64_t ad = make_desc(sb + A2_OFF + cur * 16384u);
            uint64_t bd = make_desc(sb + B2_OFF + cur * 32768u);
#pragma unroll
            for (int ks = 0; ks < 4; ks++)
                mma_f16_ss(tb, ad + ks * 2, bd + ks * 2, (kc | ks) ? 1u : 0u);
            TCG_COMMIT(sb + 8 + (cur << 3));
        }
    }
    MBAR_WAIT(sb + 8 + (((uint32_t)(NK2 - 1) & 1u) << 3), (uint32_t)(((NK2 - 1) >> 1) & 1));
    TCG_FENCE_AFTER();

    const int wg = wid >> 2;
    const int o = n0 + ((wid & 3) << 5) + lid;
    const float sc = dsc[o] * 16.0f;
#pragma unroll
    for (int cc = 0; cc < 4; cc++) {
        const int cb = wg * 128 + cc * 32;
        uint32_t dr[32];
        LDTM_X32(dr, tb + (uint32_t)cb);
        TCG_WAIT_LD();
#pragma unroll
        for (int j = 0; j < 32; j++)
            out[(size_t)(t0 + cb + j) * HID + o] = __uint_as_float(dr[j]) * sc;
    }
    __syncthreads();
    if (wid == 0) { TCG_RELQ(); TCG_DEALLOC(tb, 256); }
#endif // HAS_TCGEN05
}

extern "C" void kernel_launch(void* const* d_in, const int* in_sizes, int n_in,
                              void* d_out, int out_size) {
    const float* x  = (const float*)d_in[0];
    const int*  w1  = (const int*)d_in[1];
    const float* gus = (const float*)d_in[2];
    const int*  w2  = (const int*)d_in[3];
    const float* dsc = (const float*)d_in[4];
    float* out = (float*)d_out;

    void *p_xh, *p_w1, *p_w2;
    cudaGetSymbolAddress(&p_xh, g_xh);
    cudaGetSymbolAddress(&p_w1, g_w1h);
    cudaGetSymbolAddress(&p_w2, g_w2h);

    int n4x = TOK * HID / 4;
    int n4w1 = 2 * INTERC * HID / 4;
    int n4w2 = HID * INTERC / 4;
    cvt_f32_k<<<(n4x + 255) / 256, 256>>>((const float4*)x, (uint2*)p_xh, n4x);
    cvt_i32_k<<<(n4w1 + 255) / 256, 256>>>((const int4*)w1, (uint2*)p_w1, n4w1);
    cvt_i32_k<<<(n4w2 + 255) / 256, 256>>>((const int4*)w2, (uint2*)p_w2, n4w2);

    cudaFuncSetAttribute(ffn_gemm1, cudaFuncAttributeMaxDynamicSharedMemorySize, SMEM1);
    cudaFuncSetAttribute(ffn_gemm2, cudaFuncAttributeMaxDynamicSharedMemorySize, SMEM2);

    dim3 g1(TOK / 256, INTERC / 128);
    ffn_gemm1<<<g1, 256, SMEM1>>>(gus);
    dim3 g2(TOK / 256, HID / 128);
    ffn_gemm2<<<g2, 256, SMEM2>>>(dsc, out);
}

// round 4
// speedup vs baseline: 1.2351x; 1.2351x over previous
#include <cuda_runtime.h>
#include <cuda_fp16.h>
#include <cstdint>

#define TOK    8192
#define HID    3072
#define INTERC 8192
#define KT     64
#define NK1    (HID / KT)
#define NK2    (INTERC / KT)

#define NSTG   3

// GEMM1 smem: 3 stages of [Ag 16K | Au 16K | B 32K]
#define STG1   65536u
#define AG_OFF 1024u
#define AU_OFF (AG_OFF + 16384u)
#define B1_OFF (AU_OFF + 16384u)
#define SMEM1  (1024u + NSTG * STG1)

// GEMM2 smem: 3 stages of [A 16K | B 32K]
#define STG2   49152u
#define A2_OFF 1024u
#define B2_OFF (A2_OFF + 16384u)
#define SMEM2  (1024u + NSTG * STG2)

// kind::f16, a/b = F16, dtype = F32, M=128, N=256
#define IDESC_MMA ((1u << 4) | (32u << 17) | (8u << 24))

#if !defined(__CUDA_ARCH__) || defined(__CUDA_ARCH_FEAT_SM103_ALL) || defined(__CUDA_ARCH_FEAT_SM100_ALL) || defined(__CUDA_ARCH_FEAT_SM101_ALL)
#define HAS_TCGEN05 1
#else
#define HAS_TCGEN05 0
#endif

__device__ __align__(1024) __half g_xh [(size_t)TOK * HID];
__device__ __align__(1024) __half g_w1h[(size_t)(2 * INTERC) * HID];
__device__ __align__(1024) __half g_w2h[(size_t)HID * INTERC];
__device__ __align__(1024) __half g_hid[(size_t)TOK * INTERC];

__device__ __forceinline__ uint32_t smem_u32(const void* p) {
    uint32_t a;
    asm("{ .reg .u64 t; cvta.to.shared.u64 t, %1; cvt.u32.u64 %0, t; }" : "=r"(a) : "l"(p));
    return a;
}
#define SWZ(o) ((o) ^ (((o) >> 3) & 0x70))

__device__ __forceinline__ uint64_t make_desc(uint32_t addr) {
    const uint64_t base = (uint64_t(2) << 61) | (uint64_t(1) << 46) |
                          (uint64_t(64) << 32) | (uint64_t(1) << 16);
    return base | ((uint64_t)(addr >> 4) & 0x3FFF);
}
__device__ __forceinline__ void cpa16(uint32_t dst, const void* src) {
    asm volatile("cp.async.cg.shared.global [%0], [%1], 16;" :: "r"(dst), "l"(src));
}

#if HAS_TCGEN05
__device__ __forceinline__ void mma_f16_ss(uint32_t d, uint64_t a, uint64_t b, uint32_t en) {
    asm volatile("{\n\t.reg .pred p;\n\tsetp.ne.u32 p, %4, 0;\n\t"
        "tcgen05.mma.cta_group::1.kind::f16 [%0], %1, %2, %3, {%5, %5, %5, %5}, p;\n\t}"
        :: "r"(d), "l"(a), "l"(b), "r"(IDESC_MMA), "r"(en), "r"(0u) : "memory");
}
#define TCG_ALLOC(sa, n)  asm volatile("tcgen05.alloc.cta_group::1.sync.aligned.shared::cta.b32 [%0], %1;" :: "r"(sa), "r"((uint32_t)(n)) : "memory")
#define TCG_DEALLOC(t, n) asm volatile("tcgen05.dealloc.cta_group::1.sync.aligned.b32 %0, %1;" :: "r"(t), "r"((uint32_t)(n)))
#define TCG_RELQ()        asm volatile("tcgen05.relinquish_alloc_permit.cta_group::1.sync.aligned;")
#define TCG_COMMIT(a)     asm volatile("tcgen05.commit.cta_group::1.mbarrier::arrive::one.shared::cluster.b64 [%0];" :: "r"(a) : "memory")
#define TCG_FENCE_AFTER() asm volatile("tcgen05.fence::after_thread_sync;" ::: "memory")
#define TCG_WAIT_LD()     asm volatile("tcgen05.wait::ld.sync.aligned;" ::: "memory")

#define LDTM_X32(r, a)                                                            \
    asm volatile("tcgen05.ld.sync.aligned.32x32b.x32.b32 "                        \
        "{%0, %1, %2, %3, %4, %5, %6, %7, %8, %9, %10, %11, %12, %13, %14, %15, " \
        " %16, %17, %18, %19, %20, %21, %22, %23, %24, %25, %26, %27, %28, %29, %30, %31}, [%32];" \
        : "=r"((r)[0]),  "=r"((r)[1]),  "=r"((r)[2]),  "=r"((r)[3]),              \
          "=r"((r)[4]),  "=r"((r)[5]),  "=r"((r)[6]),  "=r"((r)[7]),              \
          "=r"((r)[8]),  "=r"((r)[9]),  "=r"((r)[10]), "=r"((r)[11]),             \
          "=r"((r)[12]), "=r"((r)[13]), "=r"((r)[14]), "=r"((r)[15]),             \
          "=r"((r)[16]), "=r"((r)[17]), "=r"((r)[18]), "=r"((r)[19]),             \
          "=r"((r)[20]), "=r"((r)[21]), "=r"((r)[22]), "=r"((r)[23]),             \
          "=r"((r)[24]), "=r"((r)[25]), "=r"((r)[26]), "=r"((r)[27]),             \
          "=r"((r)[28]), "=r"((r)[29]), "=r"((r)[30]), "=r"((r)[31])              \
        : "r"(a))
#endif

#define MBAR_INIT(a, c)   asm volatile("mbarrier.init.shared.b64 [%0], %1;" :: "r"(a), "r"((uint32_t)(c)) : "memory")
#define MBAR_WAIT(addr, ph) do {                                                 \
    uint32_t _d;                                                                 \
    asm volatile("{\n\t.reg .pred p;\n\t"                                        \
        "mbarrier.try_wait.parity.acquire.cta.shared::cta.b64 p, [%1], %2;\n\t"  \
        "selp.b32 %0, 1, 0, p;\n\t}" : "=r"(_d) : "r"(addr), "r"(ph) : "memory");\
    while (!_d)                                                                  \
        asm volatile("{\n\t.reg .pred p;\n\t"                                    \
            "mbarrier.try_wait.parity.acquire.cta.shared::cta.b64 p, [%1], %2, 0x989680;\n\t" \
            "selp.b32 %0, 1, 0, p;\n\t}" : "=r"(_d) : "r"(addr), "r"(ph) : "memory"); \
} while (0)

__device__ __forceinline__ void load_tile(uint32_t sdst, const __half* g,
                                          int ldk, int rows, int tid) {
    const int nit = rows / 32;
#pragma unroll
    for (int i = 0; i < nit; i++) {
        int idx = tid + i * 256;
        int r = idx >> 3, c = idx & 7;
        uint32_t off = (uint32_t)(r * 128 + c * 16);
        cpa16(sdst + SWZ(off), (const void*)(g + (size_t)r * ldk + c * 8));
    }
}

__global__ void __launch_bounds__(256) cvt_f32_k(const float4* __restrict__ s,
                                                 uint2* __restrict__ d, int n4) {
    int i = blockIdx.x * 256 + threadIdx.x;
    if (i >= n4) return;
    float4 v = s[i];
    __half2 a = __floats2half2_rn(v.x, v.y), b = __floats2half2_rn(v.z, v.w);
    d[i] = make_uint2(*(uint32_t*)&a, *(uint32_t*)&b);
}
__global__ void __launch_bounds__(256) cvt_i32_k(const int4* __restrict__ s,
                                                 uint2* __restrict__ d, int n4) {
    int i = blockIdx.x * 256 + threadIdx.x;
    if (i >= n4) return;
    int4 v = s[i];
    __half2 a = __floats2half2_rn((float)v.x, (float)v.y),
            b = __floats2half2_rn((float)v.z, (float)v.w);
    d[i] = make_uint2(*(uint32_t*)&a, *(uint32_t*)&b);
}

// ---------------- GEMM1: gate/up + SiLU -> g_hid (pre-scaled 1/16) -------------
__global__ void __launch_bounds__(256, 1) ffn_gemm1(const float* __restrict__ gus) {
#if HAS_TCGEN05
    extern __shared__ char smem[];
    uint32_t sb = smem_u32(smem);
    const int tid = threadIdx.x, wid = tid >> 5, lid = tid & 31;
    const int t0 = blockIdx.x * 256, g0 = blockIdx.y * 128;

    if (wid == 0) TCG_ALLOC(sb, 512);
    if (tid == 0) { MBAR_INIT(sb + 8, 1); MBAR_INIT(sb + 16, 1); MBAR_INIT(sb + 24, 1); }
    __syncthreads();
    uint32_t tb;
    asm volatile("ld.shared.b32 %0, [%1];" : "=r"(tb) : "r"(sb));

    const __half* Ag = g_w1h + (size_t)g0 * HID;
    const __half* Au = g_w1h + (size_t)(INTERC + g0) * HID;
    const __half* Bx = g_xh + (size_t)t0 * HID;

    // prologue: stages 0,1
#pragma unroll
    for (int s = 0; s < 2; s++) {
        uint32_t so = (uint32_t)s * STG1;
        load_tile(sb + AG_OFF + so, Ag + s * KT, HID, 128, tid);
        load_tile(sb + AU_OFF + so, Au + s * KT, HID, 128, tid);
        load_tile(sb + B1_OFF + so, Bx + s * KT, HID, 256, tid);
        asm volatile("cp.async.commit_group;" ::: "memory");
    }

    for (int kc = 0; kc < NK1; kc++) {
        const uint32_t cur = (uint32_t)(kc % NSTG);
        // wait data for chunk kc (at most one newer group outstanding)
        if (kc + 1 < NK1) asm volatile("cp.async.wait_group 1;" ::: "memory");
        else              asm volatile("cp.async.wait_group 0;" ::: "memory");
        asm volatile("fence.proxy.async.shared::cta;" ::: "memory");
        __syncthreads();
        if (tid == 0) {
            uint32_t so = cur * STG1;
            uint64_t ad = make_desc(sb + AG_OFF + so);
            uint64_t au = make_desc(sb + AU_OFF + so);
            uint64_t bd = make_desc(sb + B1_OFF + so);
#pragma unroll
            for (int ks = 0; ks < 4; ks++) {
                uint32_t en = (kc | ks) ? 1u : 0u;
                mma_f16_ss(tb,        ad + ks * 2, bd + ks * 2, en);
                mma_f16_ss(tb + 256u, au + ks * 2, bd + ks * 2, en);
            }
            TCG_COMMIT(sb + 8 + (cur << 3));
        }
        // prefetch chunk kc+2 into the buffer MMA(kc-1) just released
        if (kc + 2 < NK1) {
            if (kc >= 1)
                MBAR_WAIT(sb + 8 + (((uint32_t)((kc - 1) % NSTG)) << 3),
                          (uint32_t)(((kc - 1) / NSTG) & 1));
            uint32_t so = (uint32_t)((kc + 2) % NSTG) * STG1;
            load_tile(sb + AG_OFF + so, Ag + (kc + 2) * KT, HID, 128, tid);
            load_tile(sb + AU_OFF + so, Au + (kc + 2) * KT, HID, 128, tid);
            load_tile(sb + B1_OFF + so, Bx + (kc + 2) * KT, HID, 256, tid);
            asm volatile("cp.async.commit_group;" ::: "memory");
        }
    }
    MBAR_WAIT(sb + 8 + (((uint32_t)((NK1 - 1) % NSTG)) << 3),
              (uint32_t)(((NK1 - 1) / NSTG) & 1));
    TCG_FENCE_AFTER();

    const int wg = wid >> 2;
    const int o = g0 + ((wid & 3) << 5) + lid;
    const float sg = gus[o], su = gus[INTERC + o];
#pragma unroll
    for (int cc = 0; cc < 4; cc++) {
        const int cb = wg * 128 + cc * 32;
        uint32_t gr[32], ur[32];
        LDTM_X32(gr, tb + (uint32_t)cb);
        LDTM_X32(ur, tb + 256u + (uint32_t)cb);
        TCG_WAIT_LD();
#pragma unroll
        for (int j = 0; j < 32; j++) {
            float g = __uint_as_float(gr[j]) * sg;
            float u = __uint_as_float(ur[j]) * su;
            float h = g * u * 0.0625f / (1.0f + __expf(-g));
            g_hid[(size_t)(t0 + cb + j) * INTERC + o] = __float2half_rn(h);
        }
    }
    __syncthreads();
    if (wid == 0) { TCG_RELQ(); TCG_DEALLOC(tb, 512); }
#endif
}

// ---------------- GEMM2: down proj -> out f32 ---------------------------------
__global__ void __launch_bounds__(256, 1) ffn_gemm2(const float* __restrict__ dsc,
                                                    float* __restrict__ out) {
#if HAS_TCGEN05
    extern __shared__ char smem[];
    uint32_t sb = smem_u32(smem);
    const int tid = threadIdx.x, wid = tid >> 5, lid = tid & 31;
    const int t0 = blockIdx.x * 256, n0 = blockIdx.y * 128;

    if (wid == 0) TCG_ALLOC(sb, 256);
    if (tid == 0) { MBAR_INIT(sb + 8, 1); MBAR_INIT(sb + 16, 1); MBAR_INIT(sb + 24, 1); }
    __syncthreads();
    uint32_t tb;
    asm volatile("ld.shared.b32 %0, [%1];" : "=r"(tb) : "r"(sb));

    const __half* A = g_w2h + (size_t)n0 * INTERC;
    const __half* B = g_hid + (size_t)t0 * INTERC;

#pragma unroll
    for (int s = 0; s < 2; s++) {
        uint32_t so = (uint32_t)s * STG2;
        load_tile(sb + A2_OFF + so, A + s * KT, INTERC, 128, tid);
        load_tile(sb + B2_OFF + so, B + s * KT, INTERC, 256, tid);
        asm volatile("cp.async.commit_group;" ::: "memory");
    }

    for (int kc = 0; kc < NK2; kc++) {
        const uint32_t cur = (uint32_t)(kc % NSTG);
        if (kc + 1 < NK2) asm volatile("cp.async.wait_group 1;" ::: "memory");
        else              asm volatile("cp.async.wait_group 0;" ::: "memory");
        asm volatile("fence.proxy.async.shared::cta;" ::: "memory");
        __syncthreads();
        if (tid == 0) {
            uint32_t so = cur * STG2;
            uint64_t ad = make_desc(sb + A2_OFF + so);
            uint64_t bd = make_desc(sb + B2_OFF + so);
#pragma unroll
            for (int ks = 0; ks < 4; ks++)
                mma_f16_ss(tb, ad + ks * 2, bd + ks * 2, (kc | ks) ? 1u : 0u);
            TCG_COMMIT(sb + 8 + (cur << 3));
        }
        if (kc + 2 < NK2) {
            if (kc >= 1)
                MBAR_WAIT(sb + 8 + (((uint32_t)((kc - 1) % NSTG)) << 3),
                          (uint32_t)(((kc - 1) / NSTG) & 1));
            uint32_t so = (uint32_t)((kc + 2) % NSTG) * STG2;
            load_tile(sb + A2_OFF + so, A + (kc + 2) * KT, INTERC, 128, tid);
            load_tile(sb + B2_OFF + so, B + (kc + 2) * KT, INTERC, 256, tid);
            asm volatile("cp.async.commit_group;" ::: "memory");
        }
    }
    MBAR_WAIT(sb + 8 + (((uint32_t)((NK2 - 1) % NSTG)) << 3),
              (uint32_t)(((NK2 - 1) / NSTG) & 1));
    TCG_FENCE_AFTER();

    const int wg = wid >> 2;
    const int o = n0 + ((wid & 3) << 5) + lid;
    const float sc = dsc[o] * 16.0f;
#pragma unroll
    for (int cc = 0; cc < 4; cc++) {
        const int cb = wg * 128 + cc * 32;
        uint32_t dr[32];
        LDTM_X32(dr, tb + (uint32_t)cb);
        TCG_WAIT_LD();
#pragma unroll
        for (int j = 0; j < 32; j++)
            out[(size_t)(t0 + cb + j) * HID + o] = __uint_as_float(dr[j]) * sc;
    }
    __syncthreads();
    if (wid == 0) { TCG_RELQ(); TCG_DEALLOC(tb, 256); }
#endif
}

extern "C" void kernel_launch(void* const* d_in, const int* in_sizes, int n_in,
                              void* d_out, int out_size) {
    const float* x  = (const float*)d_in[0];
    const int*  w1  = (const int*)d_in[1];
    const float* gus = (const float*)d_in[2];
    const int*  w2  = (const int*)d_in[3];
    const float* dsc = (const float*)d_in[4];
    float* out = (float*)d_out;

    void *p_xh, *p_w1, *p_w2;
    cudaGetSymbolAddress(&p_xh, g_xh);
    cudaGetSymbolAddress(&p_w1, g_w1h);
    cudaGetSymbolAddress(&p_w2, g_w2h);

    int n4x = TOK * HID / 4;
    int n4w1 = 2 * INTERC * HID / 4;
    int n4w2 = HID * INTERC / 4;
    cvt_f32_k<<<(n4x + 255) / 256, 256>>>((const float4*)x, (uint2*)p_xh, n4x);
    cvt_i32_k<<<(n4w1 + 255) / 256, 256>>>((const int4*)w1, (uint2*)p_w1, n4w1);
    cvt_i32_k<<<(n4w2 + 255) / 256, 256>>>((const int4*)w2, (uint2*)p_w2, n4w2);

    cudaFuncSetAttribute(ffn_gemm1, cudaFuncAttributeMaxDynamicSharedMemorySize, SMEM1);
    cudaFuncSetAttribute(ffn_gemm2, cudaFuncAttributeMaxDynamicSharedMemorySize, SMEM2);

    dim3 g1(TOK / 256, INTERC / 128);
    ffn_gemm1<<<g1, 256, SMEM1>>>(gus);
    dim3 g2(TOK / 256, HID / 128);
    ffn_gemm2<<<g2, 256, SMEM2>>>(dsc, out);
}

// round 5
// speedup vs baseline: 1.4097x; 1.1414x over previous
#include <cuda_runtime.h>
#include <cuda_fp16.h>
#include <cstdint>

#define TOK    8192
#define HID    3072
#define INTERC 8192
#define KT     64
#define NK1    (HID / KT)
#define NK2    (INTERC / KT)

#define NSTG1  3
#define NSTG2  4

// GEMM1 smem: 3 stages of [Ag 16K | Au 16K | B 32K]
#define STG1   65536u
#define AG_OFF 1024u
#define AU_OFF (AG_OFF + 16384u)
#define B1_OFF (AU_OFF + 16384u)
#define SMEM1  (1024u + NSTG1 * STG1)

// GEMM2 smem: 4 stages of [A 16K | B 32K]
#define STG2   49152u
#define A2_OFF 1024u
#define B2_OFF (A2_OFF + 16384u)
#define SMEM2  (1024u + NSTG2 * STG2)

// kind::f16, a/b = F16, dtype = F32, M=128, N=256
#define IDESC_MMA ((1u << 4) | (32u << 17) | (8u << 24))

#if !defined(__CUDA_ARCH__) || defined(__CUDA_ARCH_FEAT_SM103_ALL) || defined(__CUDA_ARCH_FEAT_SM100_ALL) || defined(__CUDA_ARCH_FEAT_SM101_ALL)
#define HAS_TCGEN05 1
#else
#define HAS_TCGEN05 0
#endif

__device__ __align__(1024) __half g_xh [(size_t)TOK * HID];
__device__ __align__(1024) __half g_w1h[(size_t)(2 * INTERC) * HID];
__device__ __align__(1024) __half g_w2h[(size_t)HID * INTERC];
__device__ __align__(1024) __half g_hid[(size_t)TOK * INTERC];

__device__ __forceinline__ uint32_t smem_u32(const void* p) {
    uint32_t a;
    asm("{ .reg .u64 t; cvta.to.shared.u64 t, %1; cvt.u32.u64 %0, t; }" : "=r"(a) : "l"(p));
    return a;
}
#define SWZ(o) ((o) ^ (((o) >> 3) & 0x70))

// barrier slots: full[s] = sb+8+16s, empty[s] = sb+16+16s
#define FULLB(sb, s)  ((sb) + 8u + 16u * (uint32_t)(s))
#define EMPTYB(sb, s) ((sb) + 16u + 16u * (uint32_t)(s))

__device__ __forceinline__ uint64_t make_desc(uint32_t addr) {
    const uint64_t base = (uint64_t(2) << 61) | (uint64_t(1) << 46) |
                          (uint64_t(64) << 32) | (uint64_t(1) << 16);
    return base | ((uint64_t)(addr >> 4) & 0x3FFF);
}
__device__ __forceinline__ void cpa16(uint32_t dst, const void* src) {
    asm volatile("cp.async.cg.shared.global [%0], [%1], 16;" :: "r"(dst), "l"(src));
}
__device__ __forceinline__ void cpa_arrive(uint32_t mbar) {
    asm volatile("cp.async.mbarrier.arrive.noinc.shared.b64 [%0];" :: "r"(mbar) : "memory");
}

#if HAS_TCGEN05
__device__ __forceinline__ void mma_f16_ss(uint32_t d, uint64_t a, uint64_t b, uint32_t en) {
    asm volatile("{\n\t.reg .pred p;\n\tsetp.ne.u32 p, %4, 0;\n\t"
        "tcgen05.mma.cta_group::1.kind::f16 [%0], %1, %2, %3, {%5, %5, %5, %5}, p;\n\t}"
        :: "r"(d), "l"(a), "l"(b), "r"(IDESC_MMA), "r"(en), "r"(0u) : "memory");
}
#define TCG_ALLOC(sa, n)  asm volatile("tcgen05.alloc.cta_group::1.sync.aligned.shared::cta.b32 [%0], %1;" :: "r"(sa), "r"((uint32_t)(n)) : "memory")
#define TCG_DEALLOC(t, n) asm volatile("tcgen05.dealloc.cta_group::1.sync.aligned.b32 %0, %1;" :: "r"(t), "r"((uint32_t)(n)))
#define TCG_RELQ()        asm volatile("tcgen05.relinquish_alloc_permit.cta_group::1.sync.aligned;")
#define TCG_COMMIT(a)     asm volatile("tcgen05.commit.cta_group::1.mbarrier::arrive::one.shared::cluster.b64 [%0];" :: "r"(a) : "memory")
#define TCG_FENCE_AFTER() asm volatile("tcgen05.fence::after_thread_sync;" ::: "memory")
#define TCG_WAIT_LD()     asm volatile("tcgen05.wait::ld.sync.aligned;" ::: "memory")

#define LDTM_X32(r, a)                                                            \
    asm volatile("tcgen05.ld.sync.aligned.32x32b.x32.b32 "                        \
        "{%0, %1, %2, %3, %4, %5, %6, %7, %8, %9, %10, %11, %12, %13, %14, %15, " \
        " %16, %17, %18, %19, %20, %21, %22, %23, %24, %25, %26, %27, %28, %29, %30, %31}, [%32];" \
        : "=r"((r)[0]),  "=r"((r)[1]),  "=r"((r)[2]),  "=r"((r)[3]),              \
          "=r"((r)[4]),  "=r"((r)[5]),  "=r"((r)[6]),  "=r"((r)[7]),              \
          "=r"((r)[8]),  "=r"((r)[9]),  "=r"((r)[10]), "=r"((r)[11]),             \
          "=r"((r)[12]), "=r"((r)[13]), "=r"((r)[14]), "=r"((r)[15]),             \
          "=r"((r)[16]), "=r"((r)[17]), "=r"((r)[18]), "=r"((r)[19]),             \
          "=r"((r)[20]), "=r"((r)[21]), "=r"((r)[22]), "=r"((r)[23]),             \
          "=r"((r)[24]), "=r"((r)[25]), "=r"((r)[26]), "=r"((r)[27]),             \
          "=r"((r)[28]), "=r"((r)[29]), "=r"((r)[30]), "=r"((r)[31])              \
        : "r"(a))
#endif

#define MBAR_INIT(a, c)   asm volatile("mbarrier.init.shared.b64 [%0], %1;" :: "r"(a), "r"((uint32_t)(c)) : "memory")
#define MBAR_WAIT(addr, ph) do {                                                 \
    uint32_t _d;                                                                 \
    asm volatile("{\n\t.reg .pred p;\n\t"                                        \
        "mbarrier.try_wait.parity.acquire.cta.shared::cta.b64 p, [%1], %2;\n\t"  \
        "selp.b32 %0, 1, 0, p;\n\t}" : "=r"(_d) : "r"(addr), "r"(ph) : "memory");\
    while (!_d)                                                                  \
        asm volatile("{\n\t.reg .pred p;\n\t"                                    \
            "mbarrier.try_wait.parity.acquire.cta.shared::cta.b64 p, [%1], %2, 0x989680;\n\t" \
            "selp.b32 %0, 1, 0, p;\n\t}" : "=r"(_d) : "r"(addr), "r"(ph) : "memory"); \
} while (0)

// rows x 64-half K-major tile -> SW128 smem, 256 producer threads
__device__ __forceinline__ void load_tile(uint32_t sdst, const __half* g,
                                          int ldk, int rows, int tid) {
    const int nit = rows / 32;
#pragma unroll
    for (int i = 0; i < nit; i++) {
        int idx = tid + i * 256;
        int r = idx >> 3, c = idx & 7;
        uint32_t off = (uint32_t)(r * 128 + c * 16);
        cpa16(sdst + SWZ(off), (const void*)(g + (size_t)r * ldk + c * 8));
    }
}

__global__ void __launch_bounds__(256) cvt_f32_k(const float4* __restrict__ s,
                                                 uint2* __restrict__ d, int n4) {
    int i = blockIdx.x * 256 + threadIdx.x;
    if (i >= n4) return;
    float4 v = s[i];
    __half2 a = __floats2half2_rn(v.x, v.y), b = __floats2half2_rn(v.z, v.w);
    d[i] = make_uint2(*(uint32_t*)&a, *(uint32_t*)&b);
}
__global__ void __launch_bounds__(256) cvt_i32_k(const int4* __restrict__ s,
                                                 uint2* __restrict__ d, int n4) {
    int i = blockIdx.x * 256 + threadIdx.x;
    if (i >= n4) return;
    int4 v = s[i];
    __half2 a = __floats2half2_rn((float)v.x, (float)v.y),
            b = __floats2half2_rn((float)v.z, (float)v.w);
    d[i] = make_uint2(*(uint32_t*)&a, *(uint32_t*)&b);
}

// ---------------- GEMM1: gate/up + SiLU -> g_hid (pre-scaled 1/16) -------------
__global__ void __launch_bounds__(288, 1) ffn_gemm1(const float* __restrict__ gus) {
#if HAS_TCGEN05
    extern __shared__ char smem[];
    uint32_t sb = smem_u32(smem);
    const int tid = threadIdx.x, wid = tid >> 5, lid = tid & 31;
    const int t0 = blockIdx.x * 256, g0 = blockIdx.y * 128;

    if (wid == 0) TCG_ALLOC(sb, 512);
    if (tid == 0) {
#pragma unroll
        for (int s = 0; s < NSTG1; s++) {
            MBAR_INIT(FULLB(sb, s), 256);
            MBAR_INIT(EMPTYB(sb, s), 1);
        }
    }
    __syncthreads();
    uint32_t tb;
    asm volatile("ld.shared.b32 %0, [%1];" : "=r"(tb) : "r"(sb));

    const __half* Ag = g_w1h + (size_t)g0 * HID;
    const __half* Au = g_w1h + (size_t)(INTERC + g0) * HID;
    const __half* Bx = g_xh + (size_t)t0 * HID;

    if (tid < 256) {
        // producers
        for (int kc = 0; kc < NK1; kc++) {
            const int s = kc % NSTG1;
            if (kc >= NSTG1)
                MBAR_WAIT(EMPTYB(sb, s), (uint32_t)((kc / NSTG1 + 1) & 1));
            const uint32_t so = (uint32_t)s * STG1;
            load_tile(sb + AG_OFF + so, Ag + kc * KT, HID, 128, tid);
            load_tile(sb + AU_OFF + so, Au + kc * KT, HID, 128, tid);
            load_tile(sb + B1_OFF + so, Bx + kc * KT, HID, 256, tid);
            cpa_arrive(FULLB(sb, s));
        }
    } else if (tid == 256) {
        // MMA issuer
        for (int kc = 0; kc < NK1; kc++) {
            const int s = kc % NSTG1;
            MBAR_WAIT(FULLB(sb, s), (uint32_t)((kc / NSTG1) & 1));
            asm volatile("fence.proxy.async.shared::cta;" ::: "memory");
            const uint32_t so = (uint32_t)s * STG1;
            uint64_t ad = make_desc(sb + AG_OFF + so);
            uint64_t au = make_desc(sb + AU_OFF + so);
            uint64_t bd = make_desc(sb + B1_OFF + so);
#pragma unroll
            for (int ks = 0; ks < 4; ks++) {
                uint32_t en = (kc | ks) ? 1u : 0u;
                mma_f16_ss(tb,        ad + ks * 2, bd + ks * 2, en);
                mma_f16_ss(tb + 256u, au + ks * 2, bd + ks * 2, en);
            }
            TCG_COMMIT(EMPTYB(sb, s));
        }
    }

    if (tid < 256) {
        // wait final MMA: stage (NK1-1)%NSTG1, arrival #((NK1-1)/NSTG1 + 1)
        MBAR_WAIT(EMPTYB(sb, (NK1 - 1) % NSTG1), (uint32_t)(((NK1 - 1) / NSTG1) & 1));
        TCG_FENCE_AFTER();
        const int wg = wid >> 2;
        const int o = g0 + ((wid & 3) << 5) + lid;
        const float sg = gus[o], su = gus[INTERC + o];
#pragma unroll
        for (int cc = 0; cc < 4; cc++) {
            const int cb = wg * 128 + cc * 32;
            uint32_t gr[32], ur[32];
            LDTM_X32(gr, tb + (uint32_t)cb);
            LDTM_X32(ur, tb + 256u + (uint32_t)cb);
            TCG_WAIT_LD();
#pragma unroll
            for (int j = 0; j < 32; j++) {
                float g = __uint_as_float(gr[j]) * sg;
                float u = __uint_as_float(ur[j]) * su;
                float h = g * u * 0.0625f / (1.0f + __expf(-g));
                g_hid[(size_t)(t0 + cb + j) * INTERC + o] = __float2half_rn(h);
            }
        }
    }
    __syncthreads();
    if (wid == 0) { TCG_RELQ(); TCG_DEALLOC(tb, 512); }
#endif
}

// ---------------- GEMM2: down proj -> out f32 ---------------------------------
__global__ void __launch_bounds__(288, 1) ffn_gemm2(const float* __restrict__ dsc,
                                                    float* __restrict__ out) {
#if HAS_TCGEN05
    extern __shared__ char smem[];
    uint32_t sb = smem_u32(smem);
    const int tid = threadIdx.x, wid = tid >> 5, lid = tid & 31;
    const int t0 = blockIdx.x * 256, n0 = blockIdx.y * 128;

    if (wid == 0) TCG_ALLOC(sb, 256);
    if (tid == 0) {
#pragma unroll
        for (int s = 0; s < NSTG2; s++) {
            MBAR_INIT(FULLB(sb, s), 256);
            MBAR_INIT(EMPTYB(sb, s), 1);
        }
    }
    __syncthreads();
    uint32_t tb;
    asm volatile("ld.shared.b32 %0, [%1];" : "=r"(tb) : "r"(sb));

    const __half* A = g_w2h + (size_t)n0 * INTERC;
    const __half* B = g_hid + (size_t)t0 * INTERC;

    if (tid < 256) {
        for (int kc = 0; kc < NK2; kc++) {
            const int s = kc % NSTG2;
            if (kc >= NSTG2)
                MBAR_WAIT(EMPTYB(sb, s), (uint32_t)((kc / NSTG2 + 1) & 1));
            const uint32_t so = (uint32_t)s * STG2;
            load_tile(sb + A2_OFF + so, A + kc * KT, INTERC, 128, tid);
            load_tile(sb + B2_OFF + so, B + kc * KT, INTERC, 256, tid);
            cpa_arrive(FULLB(sb, s));
        }
    } else if (tid == 256) {
        for (int kc = 0; kc < NK2; kc++) {
            const int s = kc % NSTG2;
            MBAR_WAIT(FULLB(sb, s), (uint32_t)((kc / NSTG2) & 1));
            asm volatile("fence.proxy.async.shared::cta;" ::: "memory");
            const uint32_t so = (uint32_t)s * STG2;
            uint64_t ad = make_desc(sb + A2_OFF + so);
            uint64_t bd = make_desc(sb + B2_OFF + so);
#pragma unroll
            for (int ks = 0; ks < 4; ks++)
                mma_f16_ss(tb, ad + ks * 2, bd + ks * 2, (kc | ks) ? 1u : 0u);
            TCG_COMMIT(EMPTYB(sb, s));
        }
    }

    if (tid < 256) {
        MBAR_WAIT(EMPTYB(sb, (NK2 - 1) % NSTG2), (uint32_t)(((NK2 - 1) / NSTG2) & 1));
        TCG_FENCE_AFTER();
        const int wg = wid >> 2;
        const int o = n0 + ((wid & 3) << 5) + lid;
        const float sc = dsc[o] * 16.0f;
#pragma unroll
        for (int cc = 0; cc < 4; cc++) {
            const int cb = wg * 128 + cc * 32;
            uint32_t dr[32];
            LDTM_X32(dr, tb + (uint32_t)cb);
            TCG_WAIT_LD();
#pragma unroll
            for (int j = 0; j < 32; j++)
                out[(size_t)(t0 + cb + j) * HID + o] = __uint_as_float(dr[j]) * sc;
        }
    }
    __syncthreads();
    if (wid == 0) { TCG_RELQ(); TCG_DEALLOC(tb, 256); }
#endif
}

extern "C" void kernel_launch(void* const* d_in, const int* in_sizes, int n_in,
                              void* d_out, int out_size) {
    const float* x  = (const float*)d_in[0];
    const int*  w1  = (const int*)d_in[1];
    const float* gus = (const float*)d_in[2];
    const int*  w2  = (const int*)d_in[3];
    const float* dsc = (const float*)d_in[4];
    float* out = (float*)d_out;

    void *p_xh, *p_w1, *p_w2;
    cudaGetSymbolAddress(&p_xh, g_xh);
    cudaGetSymbolAddress(&p_w1, g_w1h);
    cudaGetSymbolAddress(&p_w2, g_w2h);

    int n4x = TOK * HID / 4;
    int n4w1 = 2 * INTERC * HID / 4;
    int n4w2 = HID * INTERC / 4;
    cvt_f32_k<<<(n4x + 255) / 256, 256>>>((const float4*)x, (uint2*)p_xh, n4x);
    cvt_i32_k<<<(n4w1 + 255) / 256, 256>>>((const int4*)w1, (uint2*)p_w1, n4w1);
    cvt_i32_k<<<(n4w2 + 255) / 256, 256>>>((const int4*)w2, (uint2*)p_w2, n4w2);

    cudaFuncSetAttribute(ffn_gemm1, cudaFuncAttributeMaxDynamicSharedMemorySize, SMEM1);
    cudaFuncSetAttribute(ffn_gemm2, cudaFuncAttributeMaxDynamicSharedMemorySize, SMEM2);

    dim3 g1(TOK / 256, INTERC / 128);
    ffn_gemm1<<<g1, 288, SMEM1>>>(gus);
    dim3 g2(TOK / 256, HID / 128);
    ffn_gemm2<<<g2, 288, SMEM2>>>(dsc, out);
}

// round 6
// speedup vs baseline: 1.4352x; 1.0181x over previous
#include <cuda_runtime.h>
#include <cuda_fp16.h>
#include <cstdint>

#define TOK    8192
#define HID    3072
#define INTERC 8192
#define KT     64
#define NK1    (HID / KT)     // 48
#define NK2    (INTERC / KT)  // 128

#define NSTG1  4
#define NSTG2  6

// GEMM1 stage: [Ag 16K | Au 16K | B 16K] per CTA (halves; pair covers 256x256)
#define STG1   49152u
#define SMEM1  (1024u + NSTG1 * STG1)   // 197632
// GEMM2 stage: [A 16K | B 16K]
#define STG2   32768u
#define SMEM2  (1024u + NSTG2 * STG2)   // 197632

// cg2 kind::f16: dtype=F32, a/b=F16, N=256, M=256
#define IDESC2 ((1u << 4) | (32u << 17) | (16u << 24))

#if !defined(__CUDA_ARCH__) || defined(__CUDA_ARCH_FEAT_SM103_ALL) || defined(__CUDA_ARCH_FEAT_SM100_ALL) || defined(__CUDA_ARCH_FEAT_SM101_ALL)
#define HAS_TCGEN05 1
#else
#define HAS_TCGEN05 0
#endif

__device__ __align__(1024) __half g_xh [(size_t)TOK * HID];
__device__ __align__(1024) __half g_w1h[(size_t)(2 * INTERC) * HID];
__device__ __align__(1024) __half g_w2h[(size_t)HID * INTERC];
__device__ __align__(1024) __half g_hid[(size_t)TOK * INTERC];

__device__ __forceinline__ uint32_t smem_u32(const void* p) {
    uint32_t a;
    asm("{ .reg .u64 t; cvta.to.shared.u64 t, %1; cvt.u32.u64 %0, t; }" : "=r"(a) : "l"(p));
    return a;
}
#define SWZ(o) ((o) ^ (((o) >> 3) & 0x70))

// barrier slots in smem header
#define LFULL(sb, s)  ((sb) + 32u + 32u * (uint32_t)(s))
#define EMPTYB(sb, s) ((sb) + 40u + 32u * (uint32_t)(s))
#define GFULL(sb, s)  ((sb) + 48u + 32u * (uint32_t)(s))

__device__ __forceinline__ uint64_t make_desc(uint32_t addr) {
    const uint64_t base = (uint64_t(2) << 61) | (uint64_t(1) << 46) |
                          (uint64_t(64) << 32) | (uint64_t(1) << 16);
    return base | ((uint64_t)(addr >> 4) & 0x3FFF);
}
__device__ __forceinline__ void cpa16(uint32_t dst, const void* src) {
    asm volatile("cp.async.cg.shared.global [%0], [%1], 16;" :: "r"(dst), "l"(src));
}
__device__ __forceinline__ void cpa_arrive(uint32_t mbar) {
    asm volatile("cp.async.mbarrier.arrive.noinc.shared.b64 [%0];" :: "r"(mbar) : "memory");
}

#if HAS_TCGEN05
__device__ __forceinline__ void mma2_f16_ss(uint32_t d, uint64_t a, uint64_t b, uint32_t en) {
    asm volatile("{\n\t.reg .pred p;\n\tsetp.ne.u32 p, %4, 0;\n\t"
        "tcgen05.mma.cta_group::2.kind::f16 [%0], %1, %2, %3, {%5, %5, %5, %5, %5, %5, %5, %5}, p;\n\t}"
        :: "r"(d), "l"(a), "l"(b), "r"(IDESC2), "r"(en), "r"(0u) : "memory");
}
#define TCG_ALLOC2(sa, n)  asm volatile("tcgen05.alloc.cta_group::2.sync.aligned.shared::cta.b32 [%0], %1;" :: "r"(sa), "r"((uint32_t)(n)) : "memory")
#define TCG_DEALLOC2(t, n) asm volatile("tcgen05.dealloc.cta_group::2.sync.aligned.b32 %0, %1;" :: "r"(t), "r"((uint32_t)(n)))
#define TCG_RELQ2()        asm volatile("tcgen05.relinquish_alloc_permit.cta_group::2.sync.aligned;")
#define TCG_COMMIT_MC(a)   asm volatile("tcgen05.commit.cta_group::2.mbarrier::arrive::one.shared::cluster.multicast::cluster.b64 [%0], %1;" :: "r"(a), "h"((uint16_t)3) : "memory")
#define TCG_FENCE_AFTER()  asm volatile("tcgen05.fence::after_thread_sync;" ::: "memory")
#define TCG_WAIT_LD()      asm volatile("tcgen05.wait::ld.sync.aligned;" ::: "memory")

#define LDTM_X32(r, a)                                                            \
    asm volatile("tcgen05.ld.sync.aligned.32x32b.x32.b32 "                        \
        "{%0, %1, %2, %3, %4, %5, %6, %7, %8, %9, %10, %11, %12, %13, %14, %15, " \
        " %16, %17, %18, %19, %20, %21, %22, %23, %24, %25, %26, %27, %28, %29, %30, %31}, [%32];" \
        : "=r"((r)[0]),  "=r"((r)[1]),  "=r"((r)[2]),  "=r"((r)[3]),              \
          "=r"((r)[4]),  "=r"((r)[5]),  "=r"((r)[6]),  "=r"((r)[7]),              \
          "=r"((r)[8]),  "=r"((r)[9]),  "=r"((r)[10]), "=r"((r)[11]),             \
          "=r"((r)[12]), "=r"((r)[13]), "=r"((r)[14]), "=r"((r)[15]),             \
          "=r"((r)[16]), "=r"((r)[17]), "=r"((r)[18]), "=r"((r)[19]),             \
          "=r"((r)[20]), "=r"((r)[21]), "=r"((r)[22]), "=r"((r)[23]),             \
          "=r"((r)[24]), "=r"((r)[25]), "=r"((r)[26]), "=r"((r)[27]),             \
          "=r"((r)[28]), "=r"((r)[29]), "=r"((r)[30]), "=r"((r)[31])              \
        : "r"(a))
#endif

#define MBAR_INIT(a, c)   asm volatile("mbarrier.init.shared.b64 [%0], %1;" :: "r"(a), "r"((uint32_t)(c)) : "memory")
#define MBAR_WAIT(addr, ph) do {                                                 \
    uint32_t _d;                                                                 \
    asm volatile("{\n\t.reg .pred p;\n\t"                                        \
        "mbarrier.try_wait.parity.acquire.cta.shared::cta.b64 p, [%1], %2;\n\t"  \
        "selp.b32 %0, 1, 0, p;\n\t}" : "=r"(_d) : "r"(addr), "r"(ph) : "memory");\
    while (!_d)                                                                  \
        asm volatile("{\n\t.reg .pred p;\n\t"                                    \
            "mbarrier.try_wait.parity.acquire.cta.shared::cta.b64 p, [%1], %2, 0x989680;\n\t" \
            "selp.b32 %0, 1, 0, p;\n\t}" : "=r"(_d) : "r"(addr), "r"(ph) : "memory"); \
} while (0)
#define MBAR_WAIT_CL(addr, ph) do {                                              \
    uint32_t _d;                                                                 \
    asm volatile("{\n\t.reg .pred p;\n\t"                                        \
        "mbarrier.try_wait.parity.acquire.cluster.shared::cta.b64 p, [%1], %2;\n\t" \
        "selp.b32 %0, 1, 0, p;\n\t}" : "=r"(_d) : "r"(addr), "r"(ph) : "memory");\
    while (!_d)                                                                  \
        asm volatile("{\n\t.reg .pred p;\n\t"                                    \
            "mbarrier.try_wait.parity.acquire.cluster.shared::cta.b64 p, [%1], %2, 0x989680;\n\t" \
            "selp.b32 %0, 1, 0, p;\n\t}" : "=r"(_d) : "r"(addr), "r"(ph) : "memory"); \
} while (0)
#define ARRIVE_LEADER(addr)                                                      \
    asm volatile("{\n\t.reg .b32 ra;\n\t"                                        \
        "mapa.shared::cluster.u32 ra, %0, 0;\n\t"                                \
        "mbarrier.arrive.shared::cluster.b64 _, [ra];\n\t}"                      \
        :: "r"(addr) : "memory")
#define CLUSTER_SYNC() do {                                                      \
    asm volatile("barrier.cluster.arrive.aligned;" ::: "memory");                \
    asm volatile("barrier.cluster.wait.aligned;" ::: "memory");                  \
} while (0)

// 128 rows x 64-half K-major tile -> SW128 smem, 256 producer threads
__device__ __forceinline__ void load_tile(uint32_t sdst, const __half* g,
                                          int ldk, int tid) {
#pragma unroll
    for (int i = 0; i < 4; i++) {
        int idx = tid + i * 256;
        int r = idx >> 3, c = idx & 7;
        uint32_t off = (uint32_t)(r * 128 + c * 16);
        cpa16(sdst + SWZ(off), (const void*)(g + (size_t)r * ldk + c * 8));
    }
}

__global__ void __launch_bounds__(256) cvt_f32_k(const float4* __restrict__ s,
                                                 uint2* __restrict__ d, int n4) {
    int i = blockIdx.x * 256 + threadIdx.x;
    if (i >= n4) return;
    float4 v = s[i];
    __half2 a = __floats2half2_rn(v.x, v.y), b = __floats2half2_rn(v.z, v.w);
    d[i] = make_uint2(*(uint32_t*)&a, *(uint32_t*)&b);
}
__global__ void __launch_bounds__(256) cvt_i32_k(const int4* __restrict__ s,
                                                 uint2* __restrict__ d, int n4) {
    int i = blockIdx.x * 256 + threadIdx.x;
    if (i >= n4) return;
    int4 v = s[i];
    __half2 a = __floats2half2_rn((float)v.x, (float)v.y),
            b = __floats2half2_rn((float)v.z, (float)v.w);
    d[i] = make_uint2(*(uint32_t*)&a, *(uint32_t*)&b);
}

// ---------------- GEMM1 (cg2): gate/up + SiLU -> g_hid (pre-scaled 1/16) -------
// grid (2, TOK/256, INTERC/256); pair computes [256 gate/up rows] x [256 tokens]
__global__ void __launch_bounds__(320, 1) __cluster_dims__(2, 1, 1)
ffn_gemm1(const float* __restrict__ gus) {
#if HAS_TCGEN05
    extern __shared__ char smem[];
    uint32_t sb = smem_u32(smem);
    const int tid = threadIdx.x, wid = tid >> 5, lid = tid & 31;
    uint32_t rank;
    asm("mov.u32 %0, %%cluster_ctarank;" : "=r"(rank));
    const int t0 = blockIdx.y * 256, g0 = blockIdx.z * 256;

    if (wid == 0) TCG_ALLOC2(sb, 512);
    if (tid == 0) {
#pragma unroll
        for (int s = 0; s < NSTG1; s++) {
            MBAR_INIT(LFULL(sb, s), 256);
            MBAR_INIT(EMPTYB(sb, s), 1);
            MBAR_INIT(GFULL(sb, s), 2);
        }
    }
    __syncthreads();
    uint32_t tb;
    asm volatile("ld.shared.b32 %0, [%1];" : "=r"(tb) : "r"(sb));
    CLUSTER_SYNC();

    const __half* Ag = g_w1h + (size_t)(g0 + rank * 128) * HID;
    const __half* Au = g_w1h + (size_t)(INTERC + g0 + rank * 128) * HID;
    const __half* Bx = g_xh + (size_t)(t0 + rank * 128) * HID;

    if (tid < 256) {
        for (int kc = 0; kc < NK1; kc++) {
            const int s = kc % NSTG1, r = kc / NSTG1;
            if (kc >= NSTG1) MBAR_WAIT(EMPTYB(sb, s), (uint32_t)((r + 1) & 1));
            const uint32_t base = sb + 1024u + (uint32_t)s * STG1;
            load_tile(base,          Ag + kc * KT, HID, tid);
            load_tile(base + 16384u, Au + kc * KT, HID, tid);
            load_tile(base + 32768u, Bx + kc * KT, HID, tid);
            cpa_arrive(LFULL(sb, s));
        }
    } else if (tid == 288) {   // relay warp (both ranks)
        for (int kc = 0; kc < NK1; kc++) {
            const int s = kc % NSTG1, r = kc / NSTG1;
            MBAR_WAIT(LFULL(sb, s), (uint32_t)(r & 1));
            ARRIVE_LEADER(GFULL(sb, s));
        }
    } else if (tid == 256 && rank == 0) {   // MMA issuer (leader)
        for (int kc = 0; kc < NK1; kc++) {
            const int s = kc % NSTG1, r = kc / NSTG1;
            MBAR_WAIT_CL(GFULL(sb, s), (uint32_t)(r & 1));
            asm volatile("fence.proxy.async.shared::cta;" ::: "memory");
            const uint32_t base = sb + 1024u + (uint32_t)s * STG1;
            uint64_t ad = make_desc(base);
            uint64_t au = make_desc(base + 16384u);
            uint64_t bd = make_desc(base + 32768u);
#pragma unroll
            for (int ks = 0; ks < 4; ks++) {
                uint32_t en = (kc | ks) ? 1u : 0u;
                mma2_f16_ss(tb,        ad + ks * 2, bd + ks * 2, en);
                mma2_f16_ss(tb + 256u, au + ks * 2, bd + ks * 2, en);
            }
            TCG_COMMIT_MC(EMPTYB(sb, s));
        }
    }

    if (tid < 256) {
        MBAR_WAIT(EMPTYB(sb, (NK1 - 1) % NSTG1), (uint32_t)(((NK1 - 1) / NSTG1) & 1));
        TCG_FENCE_AFTER();
        const int wg = wid >> 2;
        const int o = g0 + (int)rank * 128 + ((wid & 3) << 5) + lid;
        const float sg = gus[o], su = gus[INTERC + o];
#pragma unroll
        for (int cc = 0; cc < 4; cc++) {
            const int cb = wg * 128 + cc * 32;
            uint32_t gr[32], ur[32];
            LDTM_X32(gr, tb + (uint32_t)cb);
            LDTM_X32(ur, tb + 256u + (uint32_t)cb);
            TCG_WAIT_LD();
#pragma unroll
            for (int j = 0; j < 32; j++) {
                float g = __uint_as_float(gr[j]) * sg;
                float u = __uint_as_float(ur[j]) * su;
                float h = g * u * 0.0625f / (1.0f + __expf(-g));
                g_hid[(size_t)(t0 + cb + j) * INTERC + o] = __float2half_rn(h);
            }
        }
    }
    __syncthreads();
    CLUSTER_SYNC();
    if (wid == 0) { TCG_RELQ2(); TCG_DEALLOC2(tb, 512); }
    CLUSTER_SYNC();
#endif
}

// ---------------- GEMM2 (cg2): down proj -> out f32 ----------------------------
// grid (2, TOK/256, HID/256)
__global__ void __launch_bounds__(320, 1) __cluster_dims__(2, 1, 1)
ffn_gemm2(const float* __restrict__ dsc, float* __restrict__ out) {
#if HAS_TCGEN05
    extern __shared__ char smem[];
    uint32_t sb = smem_u32(smem);
    const int tid = threadIdx.x, wid = tid >> 5, lid = tid & 31;
    uint32_t rank;
    asm("mov.u32 %0, %%cluster_ctarank;" : "=r"(rank));
    const int t0 = blockIdx.y * 256, n0 = blockIdx.z * 256;

    if (wid == 0) TCG_ALLOC2(sb, 256);
    if (tid == 0) {
#pragma unroll
        for (int s = 0; s < NSTG2; s++) {
            MBAR_INIT(LFULL(sb, s), 256);
            MBAR_INIT(EMPTYB(sb, s), 1);
            MBAR_INIT(GFULL(sb, s), 2);
        }
    }
    __syncthreads();
    uint32_t tb;
    asm volatile("ld.shared.b32 %0, [%1];" : "=r"(tb) : "r"(sb));
    CLUSTER_SYNC();

    const __half* A = g_w2h + (size_t)(n0 + rank * 128) * INTERC;
    const __half* B = g_hid + (size_t)(t0 + rank * 128) * INTERC;

    if (tid < 256) {
        for (int kc = 0; kc < NK2; kc++) {
            const int s = kc % NSTG2, r = kc / NSTG2;
            if (kc >= NSTG2) MBAR_WAIT(EMPTYB(sb, s), (uint32_t)((r + 1) & 1));
            const uint32_t base = sb + 1024u + (uint32_t)s * STG2;
            load_tile(base,          A + kc * KT, INTERC, tid);
            load_tile(base + 16384u, B + kc * KT, INTERC, tid);
            cpa_arrive(LFULL(sb, s));
        }
    } else if (tid == 288) {
        for (int kc = 0; kc < NK2; kc++) {
            const int s = kc % NSTG2, r = kc / NSTG2;
            MBAR_WAIT(LFULL(sb, s), (uint32_t)(r & 1));
            ARRIVE_LEADER(GFULL(sb, s));
        }
    } else if (tid == 256 && rank == 0) {
        for (int kc = 0; kc < NK2; kc++) {
            const int s = kc % NSTG2, r = kc / NSTG2;
            MBAR_WAIT_CL(GFULL(sb, s), (uint32_t)(r & 1));
            asm volatile("fence.proxy.async.shared::cta;" ::: "memory");
            const uint32_t base = sb + 1024u + (uint32_t)s * STG2;
            uint64_t ad = make_desc(base);
            uint64_t bd = make_desc(base + 16384u);
#pragma unroll
            for (int ks = 0; ks < 4; ks++)
                mma2_f16_ss(tb, ad + ks * 2, bd + ks * 2, (kc | ks) ? 1u : 0u);
            TCG_COMMIT_MC(EMPTYB(sb, s));
        }
    }

    if (tid < 256) {
        MBAR_WAIT(EMPTYB(sb, (NK2 - 1) % NSTG2), (uint32_t)(((NK2 - 1) / NSTG2) & 1));
        TCG_FENCE_AFTER();
        const int wg = wid >> 2;
        const int o = n0 + (int)rank * 128 + ((wid & 3) << 5) + lid;
        const float sc = dsc[o] * 16.0f;
#pragma unroll
        for (int cc = 0; cc < 4; cc++) {
            const int cb = wg * 128 + cc * 32;
            uint32_t dr[32];
            LDTM_X32(dr, tb + (uint32_t)cb);
            TCG_WAIT_LD();
#pragma unroll
            for (int j = 0; j < 32; j++)
                out[(size_t)(t0 + cb + j) * HID + o] = __uint_as_float(dr[j]) * sc;
        }
    }
    __syncthreads();
    CLUSTER_SYNC();
    if (wid == 0) { TCG_RELQ2(); TCG_DEALLOC2(tb, 256); }
    CLUSTER_SYNC();
#endif
}

extern "C" void kernel_launch(void* const* d_in, const int* in_sizes, int n_in,
                              void* d_out, int out_size) {
    const float* x  = (const float*)d_in[0];
    const int*  w1  = (const int*)d_in[1];
    const float* gus = (const float*)d_in[2];
    const int*  w2  = (const int*)d_in[3];
    const float* dsc = (const float*)d_in[4];
    float* out = (float*)d_out;

    void *p_xh, *p_w1, *p_w2;
    cudaGetSymbolAddress(&p_xh, g_xh);
    cudaGetSymbolAddress(&p_w1, g_w1h);
    cudaGetSymbolAddress(&p_w2, g_w2h);

    int n4x = TOK * HID / 4;
    int n4w1 = 2 * INTERC * HID / 4;
    int n4w2 = HID * INTERC / 4;
    cvt_f32_k<<<(n4x + 255) / 256, 256>>>((const float4*)x, (uint2*)p_xh, n4x);
    cvt_i32_k<<<(n4w1 + 255) / 256, 256>>>((const int4*)w1, (uint2*)p_w1, n4w1);
    cvt_i32_k<<<(n4w2 + 255) / 256, 256>>>((const int4*)w2, (uint2*)p_w2, n4w2);

    cudaFuncSetAttribute(ffn_gemm1, cudaFuncAttributeMaxDynamicSharedMemorySize, SMEM1);
    cudaFuncSetAttribute(ffn_gemm2, cudaFuncAttributeMaxDynamicSharedMemorySize, SMEM2);

    dim3 g1(2, TOK / 256, INTERC / 256);
    ffn_gemm1<<<g1, 320, SMEM1>>>(gus);
    dim3 g2(2, TOK / 256, HID / 256);
    ffn_gemm2<<<g2, 320, SMEM2>>>(dsc, out);
}

// round 9
// speedup vs baseline: 1.4451x; 1.0069x over previous
#include <cuda_runtime.h>
#include <cuda_fp16.h>
#include <cstdint>

#define TOK    8192
#define HID    3072
#define INTERC 8192
#define KT     64
#define NK1    (HID / KT)     // 48
#define NK2    (INTERC / KT)  // 128
#define TILEB  16384u         // one 128x64 f16 tile, swizzled, bytes

#define NSTG1  4
#define NSTG2  6

#define STG1   49152u
#define SMEM1  (1024u + NSTG1 * STG1)
#define STG2   32768u
#define SMEM2  (1024u + NSTG2 * STG2)

// cg2 kind::f16: dtype=F32, a/b=F16, N=256, M=256
#define IDESC2 ((1u << 4) | (32u << 17) | (16u << 24))

#if !defined(__CUDA_ARCH__) || defined(__CUDA_ARCH_FEAT_SM103_ALL) || defined(__CUDA_ARCH_FEAT_SM100_ALL) || defined(__CUDA_ARCH_FEAT_SM101_ALL)
#define HAS_TCGEN05 1
#else
#define HAS_TCGEN05 0
#endif

// tiled+swizzled scratch: [rowblock][kchunk][16KB tile]
__device__ __align__(1024) __half g_xh [(size_t)TOK * HID];
__device__ __align__(1024) __half g_w1h[(size_t)(2 * INTERC) * HID];
__device__ __align__(1024) __half g_w2h[(size_t)HID * INTERC];
__device__ __align__(1024) __half g_hid[(size_t)TOK * INTERC];

__device__ __forceinline__ uint32_t smem_u32(const void* p) {
    uint32_t a;
    asm("{ .reg .u64 t; cvta.to.shared.u64 t, %1; cvt.u32.u64 %0, t; }" : "=r"(a) : "l"(p));
    return a;
}
#define SWZ(o) ((o) ^ (((o) >> 3) & 0x70))

#define LFULL(sb, s)  ((sb) + 32u + 32u * (uint32_t)(s))
#define EMPTYB(sb, s) ((sb) + 40u + 32u * (uint32_t)(s))
#define GFULL(sb, s)  ((sb) + 48u + 32u * (uint32_t)(s))

__device__ __forceinline__ uint64_t make_desc(uint32_t addr) {
    const uint64_t base = (uint64_t(2) << 61) | (uint64_t(1) << 46) |
                          (uint64_t(64) << 32) | (uint64_t(1) << 16);
    return base | ((uint64_t)(addr >> 4) & 0x3FFF);
}
__device__ __forceinline__ void cpa16(uint32_t dst, const void* src) {
    asm volatile("cp.async.cg.shared.global [%0], [%1], 16;" :: "r"(dst), "l"(src));
}
__device__ __forceinline__ void cpa_arrive(uint32_t mbar) {
    asm volatile("cp.async.mbarrier.arrive.noinc.shared.b64 [%0];" :: "r"(mbar) : "memory");
}
// pre-swizzled contiguous 16KB tile: straight memcpy, 256 threads x 4 x 16B
__device__ __forceinline__ void copy_tile(uint32_t sdst, const char* src, int tid) {
#pragma unroll
    for (int i = 0; i < 4; i++) {
        uint32_t off = (uint32_t)(tid * 16 + i * 4096);
        cpa16(sdst + off, src + off);
    }
}

#if HAS_TCGEN05
__device__ __forceinline__ void mma2_f16_ss(uint32_t d, uint64_t a, uint64_t b, uint32_t en) {
    asm volatile("{\n\t.reg .pred p;\n\tsetp.ne.u32 p, %4, 0;\n\t"
        "tcgen05.mma.cta_group::2.kind::f16 [%0], %1, %2, %3, {%5, %5, %5, %5, %5, %5, %5, %5}, p;\n\t}"
        :: "r"(d), "l"(a), "l"(b), "r"(IDESC2), "r"(en), "r"(0u) : "memory");
}
#define TCG_ALLOC2(sa, n)  asm volatile("tcgen05.alloc.cta_group::2.sync.aligned.shared::cta.b32 [%0], %1;" :: "r"(sa), "r"((uint32_t)(n)) : "memory")
#define TCG_DEALLOC2(t, n) asm volatile("tcgen05.dealloc.cta_group::2.sync.aligned.b32 %0, %1;" :: "r"(t), "r"((uint32_t)(n)))
#define TCG_RELQ2()        asm volatile("tcgen05.relinquish_alloc_permit.cta_group::2.sync.aligned;")
#define TCG_COMMIT_MC(a)   asm volatile("tcgen05.commit.cta_group::2.mbarrier::arrive::one.shared::cluster.multicast::cluster.b64 [%0], %1;" :: "r"(a), "h"((uint16_t)3) : "memory")
#define TCG_FENCE_AFTER()  asm volatile("tcgen05.fence::after_thread_sync;" ::: "memory")
#define TCG_WAIT_LD()      asm volatile("tcgen05.wait::ld.sync.aligned;" ::: "memory")

#define LDTM_X32(r, a)                                                            \
    asm volatile("tcgen05.ld.sync.aligned.32x32b.x32.b32 "                        \
        "{%0, %1, %2, %3, %4, %5, %6, %7, %8, %9, %10, %11, %12, %13, %14, %15, " \
        " %16, %17, %18, %19, %20, %21, %22, %23, %24, %25, %26, %27, %28, %29, %30, %31}, [%32];" \
        : "=r"((r)[0]),  "=r"((r)[1]),  "=r"((r)[2]),  "=r"((r)[3]),              \
          "=r"((r)[4]),  "=r"((r)[5]),  "=r"((r)[6]),  "=r"((r)[7]),              \
          "=r"((r)[8]),  "=r"((r)[9]),  "=r"((r)[10]), "=r"((r)[11]),             \
          "=r"((r)[12]), "=r"((r)[13]), "=r"((r)[14]), "=r"((r)[15]),             \
          "=r"((r)[16]), "=r"((r)[17]), "=r"((r)[18]), "=r"((r)[19]),             \
          "=r"((r)[20]), "=r"((r)[21]), "=r"((r)[22]), "=r"((r)[23]),             \
          "=r"((r)[24]), "=r"((r)[25]), "=r"((r)[26]), "=r"((r)[27]),             \
          "=r"((r)[28]), "=r"((r)[29]), "=r"((r)[30]), "=r"((r)[31])              \
        : "r"(a))
#endif

#define MBAR_INIT(a, c)   asm volatile("mbarrier.init.shared.b64 [%0], %1;" :: "r"(a), "r"((uint32_t)(c)) : "memory")
#define MBAR_WAIT(addr, ph) do {                                                 \
    uint32_t _d;                                                                 \
    asm volatile("{\n\t.reg .pred p;\n\t"                                        \
        "mbarrier.try_wait.parity.acquire.cta.shared::cta.b64 p, [%1], %2;\n\t"  \
        "selp.b32 %0, 1, 0, p;\n\t}" : "=r"(_d) : "r"(addr), "r"(ph) : "memory");\
    while (!_d)                                                                  \
        asm volatile("{\n\t.reg .pred p;\n\t"                                    \
            "mbarrier.try_wait.parity.acquire.cta.shared::cta.b64 p, [%1], %2, 0x989680;\n\t" \
            "selp.b32 %0, 1, 0, p;\n\t}" : "=r"(_d) : "r"(addr), "r"(ph) : "memory"); \
} while (0)
#define MBAR_WAIT_CL(addr, ph) do {                                              \
    uint32_t _d;                                                                 \
    asm volatile("{\n\t.reg .pred p;\n\t"                                        \
        "mbarrier.try_wait.parity.acquire.cluster.shared::cta.b64 p, [%1], %2;\n\t" \
        "selp.b32 %0, 1, 0, p;\n\t}" : "=r"(_d) : "r"(addr), "r"(ph) : "memory");\
    while (!_d)                                                                  \
        asm volatile("{\n\t.reg .pred p;\n\t"                                    \
            "mbarrier.try_wait.parity.acquire.cluster.shared::cta.b64 p, [%1], %2, 0x989680;\n\t" \
            "selp.b32 %0, 1, 0, p;\n\t}" : "=r"(_d) : "r"(addr), "r"(ph) : "memory"); \
} while (0)
#define ARRIVE_LEADER(addr)                                                      \
    asm volatile("{\n\t.reg .b32 ra;\n\t"                                        \
        "mapa.shared::cluster.u32 ra, %0, 0;\n\t"                                \
        "mbarrier.arrive.shared::cluster.b64 _, [ra];\n\t}"                      \
        :: "r"(addr) : "memory")
#define CLUSTER_SYNC() do {                                                      \
    asm volatile("barrier.cluster.arrive.aligned;" ::: "memory");                \
    asm volatile("barrier.cluster.wait.aligned;" ::: "memory");                  \
} while (0)

// ---- converts: row-major -> tiled [row/128][col/64][16KB SW128-swizzled] ------
__global__ void __launch_bounds__(256) cvt_i32_t(const int* __restrict__ s,
                                                 __half* __restrict__ d,
                                                 int cols, unsigned ngrp) {
    unsigned i = blockIdx.x * 256u + threadIdx.x;
    if (i >= ngrp) return;
    unsigned e = i * 8u;
    unsigned row = e / (unsigned)cols, col = e % (unsigned)cols;
    const int4* p = (const int4*)(s + (size_t)row * cols + col);
    int4 a = p[0], b = p[1];
    __half2 h0 = __floats2half2_rn((float)a.x, (float)a.y);
    __half2 h1 = __floats2half2_rn((float)a.z, (float)a.w);
    __half2 h2 = __floats2half2_rn((float)b.x, (float)b.y);
    __half2 h3 = __floats2half2_rn((float)b.z, (float)b.w);
    uint4 v = make_uint4(*(uint32_t*)&h0, *(uint32_t*)&h1, *(uint32_t*)&h2, *(uint32_t*)&h3);
    unsigned nkc = (unsigned)cols >> 6;
    size_t tile = (size_t)(row >> 7) * nkc + (col >> 6);
    uint32_t off = (row & 127u) * 128u + (col & 63u) * 2u;
    *(uint4*)((char*)d + tile * TILEB + SWZ(off)) = v;
}
__global__ void __launch_bounds__(256) cvt_f32_t(const float* __restrict__ s,
                                                 __half* __restrict__ d,
                                                 int cols, unsigned ngrp) {
    unsigned i = blockIdx.x * 256u + threadIdx.x;
    if (i >= ngrp) return;
    unsigned e = i * 8u;
    unsigned row = e / (unsigned)cols, col = e % (unsigned)cols;
    const float4* p = (const float4*)(s + (size_t)row * cols + col);
    float4 a = p[0], b = p[1];
    __half2 h0 = __floats2half2_rn(a.x, a.y);
    __half2 h1 = __floats2half2_rn(a.z, a.w);
    __half2 h2 = __floats2half2_rn(b.x, b.y);
    __half2 h3 = __floats2half2_rn(b.z, b.w);
    uint4 v = make_uint4(*(uint32_t*)&h0, *(uint32_t*)&h1, *(uint32_t*)&h2, *(uint32_t*)&h3);
    unsigned nkc = (unsigned)cols >> 6;
    size_t tile = (size_t)(row >> 7) * nkc + (col >> 6);
    uint32_t off = (row & 127u) * 128u + (col & 63u) * 2u;
    *(uint4*)((char*)d + tile * TILEB + SWZ(off)) = v;
}

// ---------------- GEMM1 (cg2, cp.async from tiled gmem) ------------------------
__global__ void __launch_bounds__(320, 1) __cluster_dims__(2, 1, 1)
ffn_gemm1(const float* __restrict__ gus) {
#if HAS_TCGEN05
    extern __shared__ char smem[];
    uint32_t sb = smem_u32(smem);
    const int tid = threadIdx.x, wid = tid >> 5, lid = tid & 31;
    uint32_t rank;
    asm("mov.u32 %0, %%cluster_ctarank;" : "=r"(rank));
    const int by = blockIdx.y, bz = blockIdx.z;
    const int t0 = by * 256, g0 = bz * 256;

    if (wid == 0) TCG_ALLOC2(sb, 512);
    if (tid == 0) {
#pragma unroll
        for (int s = 0; s < NSTG1; s++) {
            MBAR_INIT(LFULL(sb, s), 256);
            MBAR_INIT(EMPTYB(sb, s), 1);
            MBAR_INIT(GFULL(sb, s), 2);
        }
    }
    __syncthreads();
    uint32_t tb;
    asm volatile("ld.shared.b32 %0, [%1];" : "=r"(tb) : "r"(sb));
    CLUSTER_SYNC();

    const char* wb = (const char*)g_w1h;
    const char* xb = (const char*)g_xh;
    const size_t rbg = (size_t)(2 * bz + (int)rank);
    const size_t rbu = (size_t)(INTERC / 128 + 2 * bz + (int)rank);
    const size_t rbx = (size_t)(2 * by + (int)rank);

    if (tid < 256) {
        // producers
        for (int kc = 0; kc < NK1; kc++) {
            const int s = kc % NSTG1, r = kc / NSTG1;
            if (kc >= NSTG1) MBAR_WAIT(EMPTYB(sb, s), (uint32_t)((r + 1) & 1));
            const uint32_t base = sb + 1024u + (uint32_t)s * STG1;
            copy_tile(base,             wb + (rbg * NK1 + kc) * TILEB, tid);
            copy_tile(base + TILEB,     wb + (rbu * NK1 + kc) * TILEB, tid);
            copy_tile(base + 2 * TILEB, xb + (rbx * NK1 + kc) * TILEB, tid);
            cpa_arrive(LFULL(sb, s));
        }
    } else if (tid == 288) {
        // relay: local full -> leader gfull
        for (int kc = 0; kc < NK1; kc++) {
            const int s = kc % NSTG1, r = kc / NSTG1;
            MBAR_WAIT(LFULL(sb, s), (uint32_t)(r & 1));
            ARRIVE_LEADER(GFULL(sb, s));
        }
    } else if (tid == 256 && rank == 0) {
        // MMA issuer (leader)
        for (int kc = 0; kc < NK1; kc++) {
            const int s = kc % NSTG1, r = kc / NSTG1;
            MBAR_WAIT_CL(GFULL(sb, s), (uint32_t)(r & 1));
            asm volatile("fence.proxy.async.shared::cta;" ::: "memory");
            const uint32_t base = sb + 1024u + (uint32_t)s * STG1;
            uint64_t ad = make_desc(base);
            uint64_t au = make_desc(base + TILEB);
            uint64_t bd = make_desc(base + 2 * TILEB);
#pragma unroll
            for (int ks = 0; ks < 4; ks++) {
                uint32_t en = (kc | ks) ? 1u : 0u;
                mma2_f16_ss(tb,        ad + ks * 2, bd + ks * 2, en);
                mma2_f16_ss(tb + 256u, au + ks * 2, bd + ks * 2, en);
            }
            TCG_COMMIT_MC(EMPTYB(sb, s));
        }
    }

    if (tid < 256) {
        MBAR_WAIT(EMPTYB(sb, (NK1 - 1) % NSTG1), (uint32_t)(((NK1 - 1) / NSTG1) & 1));
        TCG_FENCE_AFTER();
        const int wg = wid >> 2;
        const int o = g0 + (int)rank * 128 + ((wid & 3) << 5) + lid;
        const float sg = gus[o], su = gus[INTERC + o];
        char* hb = (char*)g_hid;
        const size_t tilebase = ((size_t)(2 * by + wg) * NK2 + (size_t)(o >> 6)) * TILEB;
        const uint32_t oc = (uint32_t)(o & 63) * 2u;
#pragma unroll
        for (int cc = 0; cc < 4; cc++) {
            const int cb = wg * 128 + cc * 32;
            uint32_t gr[32], ur[32];
            LDTM_X32(gr, tb + (uint32_t)cb);
            LDTM_X32(ur, tb + 256u + (uint32_t)cb);
            TCG_WAIT_LD();
#pragma unroll
            for (int j = 0; j < 32; j++) {
                float g = __uint_as_float(gr[j]) * sg;
                float u = __uint_as_float(ur[j]) * su;
                float h = g * u * 0.0625f / (1.0f + __expf(-g));
                uint32_t off = (uint32_t)(cc * 32 + j) * 128u + oc;
                *(__half*)(hb + tilebase + SWZ(off)) = __float2half_rn(h);
            }
        }
    }
    __syncthreads();
    CLUSTER_SYNC();
    if (wid == 0) { TCG_RELQ2(); TCG_DEALLOC2(tb, 512); }
    CLUSTER_SYNC();
#endif
}

// ---------------- GEMM2 (cg2, cp.async from tiled gmem) ------------------------
__global__ void __launch_bounds__(320, 1) __cluster_dims__(2, 1, 1)
ffn_gemm2(const float* __restrict__ dsc, float* __restrict__ out) {
#if HAS_TCGEN05
    extern __shared__ char smem[];
    uint32_t sb = smem_u32(smem);
    const int tid = threadIdx.x, wid = tid >> 5, lid = tid & 31;
    uint32_t rank;
    asm("mov.u32 %0, %%cluster_ctarank;" : "=r"(rank));
    const int by = blockIdx.y, bz = blockIdx.z;
    const int t0 = by * 256, n0 = bz * 256;

    if (wid == 0) TCG_ALLOC2(sb, 256);
    if (tid == 0) {
#pragma unroll
        for (int s = 0; s < NSTG2; s++) {
            MBAR_INIT(LFULL(sb, s), 256);
            MBAR_INIT(EMPTYB(sb, s), 1);
            MBAR_INIT(GFULL(sb, s), 2);
        }
    }
    __syncthreads();
    uint32_t tb;
    asm volatile("ld.shared.b32 %0, [%1];" : "=r"(tb) : "r"(sb));
    CLUSTER_SYNC();

    const char* wb = (const char*)g_w2h;
    const char* hbs = (const char*)g_hid;
    const size_t rba = (size_t)(2 * bz + (int)rank);
    const size_t rbb = (size_t)(2 * by + (int)rank);

    if (tid < 256) {
        for (int kc = 0; kc < NK2; kc++) {
            const int s = kc % NSTG2, r = kc / NSTG2;
            if (kc >= NSTG2) MBAR_WAIT(EMPTYB(sb, s), (uint32_t)((r + 1) & 1));
            const uint32_t base = sb + 1024u + (uint32_t)s * STG2;
            copy_tile(base,         wb  + (rba * NK2 + kc) * TILEB, tid);
            copy_tile(base + TILEB, hbs + (rbb * NK2 + kc) * TILEB, tid);
            cpa_arrive(LFULL(sb, s));
        }
    } else if (tid == 288) {
        for (int kc = 0; kc < NK2; kc++) {
            const int s = kc % NSTG2, r = kc / NSTG2;
            MBAR_WAIT(LFULL(sb, s), (uint32_t)(r & 1));
            ARRIVE_LEADER(GFULL(sb, s));
        }
    } else if (tid == 256 && rank == 0) {
        for (int kc = 0; kc < NK2; kc++) {
            const int s = kc % NSTG2, r = kc / NSTG2;
            MBAR_WAIT_CL(GFULL(sb, s), (uint32_t)(r & 1));
            asm volatile("fence.proxy.async.shared::cta;" ::: "memory");
            const uint32_t base = sb + 1024u + (uint32_t)s * STG2;
            uint64_t ad = make_desc(base);
            uint64_t bd = make_desc(base + TILEB);
#pragma unroll
            for (int ks = 0; ks < 4; ks++)
                mma2_f16_ss(tb, ad + ks * 2, bd + ks * 2, (kc | ks) ? 1u : 0u);
            TCG_COMMIT_MC(EMPTYB(sb, s));
        }
    }

    if (tid < 256) {
        MBAR_WAIT(EMPTYB(sb, (NK2 - 1) % NSTG2), (uint32_t)(((NK2 - 1) / NSTG2) & 1));
        TCG_FENCE_AFTER();
        const int wg = wid >> 2;
        const int o = n0 + (int)rank * 128 + ((wid & 3) << 5) + lid;
        const float sc = dsc[o] * 16.0f;
#pragma unroll
        for (int cc = 0; cc < 4; cc++) {
            const int cb = wg * 128 + cc * 32;
            uint32_t dr[32];
            LDTM_X32(dr, tb + (uint32_t)cb);
            TCG_WAIT_LD();
#pragma unroll
            for (int j = 0; j < 32; j++)
                out[(size_t)(t0 + cb + j) * HID + o] = __uint_as_float(dr[j]) * sc;
        }
    }
    __syncthreads();
    CLUSTER_SYNC();
    if (wid == 0) { TCG_RELQ2(); TCG_DEALLOC2(tb, 256); }
    CLUSTER_SYNC();
#endif
}

extern "C" void kernel_launch(void* const* d_in, const int* in_sizes, int n_in,
                              void* d_out, int out_size) {
    const float* x  = (const float*)d_in[0];
    const int*  w1  = (const int*)d_in[1];
    const float* gus = (const float*)d_in[2];
    const int*  w2  = (const int*)d_in[3];
    const float* dsc = (const float*)d_in[4];
    float* out = (float*)d_out;

    void *p_xh, *p_w1, *p_w2;
    cudaGetSymbolAddress(&p_xh, g_xh);
    cudaGetSymbolAddress(&p_w1, g_w1h);
    cudaGetSymbolAddress(&p_w2, g_w2h);

    unsigned gx = (unsigned)((size_t)TOK * HID / 8);
    unsigned gw1 = (unsigned)((size_t)2 * INTERC * HID / 8);
    unsigned gw2 = (unsigned)((size_t)HID * INTERC / 8);
    cvt_f32_t<<<(gx + 255) / 256, 256>>>(x, (__half*)p_xh, HID, gx);
    cvt_i32_t<<<(gw1 + 255) / 256, 256>>>(w1, (__half*)p_w1, HID, gw1);
    cvt_i32_t<<<(gw2 + 255) / 256, 256>>>(w2, (__half*)p_w2, INTERC, gw2);

    cudaFuncSetAttribute(ffn_gemm1, cudaFuncAttributeMaxDynamicSharedMemorySize, SMEM1);
    cudaFuncSetAttribute(ffn_gemm2, cudaFuncAttributeMaxDynamicSharedMemorySize, SMEM2);

    dim3 g1(2, TOK / 256, INTERC / 256);
    ffn_gemm1<<<g1, 320, SMEM1>>>(gus);
    dim3 g2(2, TOK / 256, HID / 256);
    ffn_gemm2<<<g2, 320, SMEM2>>>(dsc, out);
}

// round 12
// speedup vs baseline: 1.4652x; 1.0139x over previous
#include <cuda_runtime.h>
#include <cuda_fp16.h>
#include <cstdint>

#define TOK    8192
#define HID    3072
#define INTERC 8192
#define KT     64
#define NK1    (HID / KT)     // 48
#define NK2    (INTERC / KT)  // 128
#define TILEB  16384u         // one 128x64 f16 tile, swizzled, bytes

// GEMM1: weight ring (Ag+Au, 32KB stages) + B ring (16KB stages)
#define NSW1   4
#define NSB1   6
#define W1_OFF 1024u
#define B1_OFF (1024u + NSW1 * 32768u)          // 132096
#define SMEM1  (B1_OFF + NSB1 * 16384u)          // 230400
// GEMM2: 6 stages of [A 16K | B 16K]
#define NSTG2  6
#define STG2   32768u
#define SMEM2  (1024u + NSTG2 * STG2)            // 197632

// cg2 kind::f16: dtype=F32, a/b=F16, N=256, M=256
#define IDESC2 ((1u << 4) | (32u << 17) | (16u << 24))

#if !defined(__CUDA_ARCH__) || defined(__CUDA_ARCH_FEAT_SM103_ALL) || defined(__CUDA_ARCH_FEAT_SM100_ALL) || defined(__CUDA_ARCH_FEAT_SM101_ALL)
#define HAS_TCGEN05 1
#else
#define HAS_TCGEN05 0
#endif

// tiled+swizzled scratch: [rowblock][kchunk][16KB tile]
__device__ __align__(1024) __half g_xh [(size_t)TOK * HID];
__device__ __align__(1024) __half g_w1h[(size_t)(2 * INTERC) * HID];
__device__ __align__(1024) __half g_w2h[(size_t)HID * INTERC];
__device__ __align__(1024) __half g_hid[(size_t)TOK * INTERC];

__device__ __forceinline__ uint32_t smem_u32(const void* p) {
    uint32_t a;
    asm("{ .reg .u64 t; cvta.to.shared.u64 t, %1; cvt.u32.u64 %0, t; }" : "=r"(a) : "l"(p));
    return a;
}
#define SWZ(o) ((o) ^ (((o) >> 3) & 0x70))

// GEMM1 barrier slots (header): wfull[4]@32, wempty[4]@64, bfull[6]@96,
// bempty[6]@144, gfull[4]@192
#define WFULL(sb, s)   ((sb) + 32u + 8u * (uint32_t)(s))
#define WEMPTY(sb, s)  ((sb) + 64u + 8u * (uint32_t)(s))
#define BFULL(sb, s)   ((sb) + 96u + 8u * (uint32_t)(s))
#define BEMPTY(sb, s)  ((sb) + 144u + 8u * (uint32_t)(s))
#define GFULL1(sb, s)  ((sb) + 192u + 8u * (uint32_t)(s))
// GEMM2 slots (as R9)
#define LFULL(sb, s)   ((sb) + 32u + 32u * (uint32_t)(s))
#define EMPTYB(sb, s)  ((sb) + 40u + 32u * (uint32_t)(s))
#define GFULL(sb, s)   ((sb) + 48u + 32u * (uint32_t)(s))

__device__ __forceinline__ uint64_t make_desc(uint32_t addr) {
    const uint64_t base = (uint64_t(2) << 61) | (uint64_t(1) << 46) |
                          (uint64_t(64) << 32) | (uint64_t(1) << 16);
    return base | ((uint64_t)(addr >> 4) & 0x3FFF);
}
__device__ __forceinline__ void cpa16(uint32_t dst, const void* src) {
    asm volatile("cp.async.cg.shared.global [%0], [%1], 16;" :: "r"(dst), "l"(src));
}
__device__ __forceinline__ void cpa_arrive(uint32_t mbar) {
    asm volatile("cp.async.mbarrier.arrive.noinc.shared.b64 [%0];" :: "r"(mbar) : "memory");
}
// pre-swizzled contiguous 16KB tile: straight memcpy, 256 threads x 4 x 16B
__device__ __forceinline__ void copy_tile(uint32_t sdst, const char* src, int tid) {
#pragma unroll
    for (int i = 0; i < 4; i++) {
        uint32_t off = (uint32_t)(tid * 16 + i * 4096);
        cpa16(sdst + off, src + off);
    }
}

#if HAS_TCGEN05
__device__ __forceinline__ void mma2_f16_ss(uint32_t d, uint64_t a, uint64_t b, uint32_t en) {
    asm volatile("{\n\t.reg .pred p;\n\tsetp.ne.u32 p, %4, 0;\n\t"
        "tcgen05.mma.cta_group::2.kind::f16 [%0], %1, %2, %3, {%5, %5, %5, %5, %5, %5, %5, %5}, p;\n\t}"
        :: "r"(d), "l"(a), "l"(b), "r"(IDESC2), "r"(en), "r"(0u) : "memory");
}
#define TCG_ALLOC2(sa, n)  asm volatile("tcgen05.alloc.cta_group::2.sync.aligned.shared::cta.b32 [%0], %1;" :: "r"(sa), "r"((uint32_t)(n)) : "memory")
#define TCG_DEALLOC2(t, n) asm volatile("tcgen05.dealloc.cta_group::2.sync.aligned.b32 %0, %1;" :: "r"(t), "r"((uint32_t)(n)))
#define TCG_RELQ2()        asm volatile("tcgen05.relinquish_alloc_permit.cta_group::2.sync.aligned;")
#define TCG_COMMIT_MC(a)   asm volatile("tcgen05.commit.cta_group::2.mbarrier::arrive::one.shared::cluster.multicast::cluster.b64 [%0], %1;" :: "r"(a), "h"((uint16_t)3) : "memory")
#define TCG_FENCE_AFTER()  asm volatile("tcgen05.fence::after_thread_sync;" ::: "memory")
#define TCG_WAIT_LD()      asm volatile("tcgen05.wait::ld.sync.aligned;" ::: "memory")

#define LDTM_X32(r, a)                                                            \
    asm volatile("tcgen05.ld.sync.aligned.32x32b.x32.b32 "                        \
        "{%0, %1, %2, %3, %4, %5, %6, %7, %8, %9, %10, %11, %12, %13, %14, %15, " \
        " %16, %17, %18, %19, %20, %21, %22, %23, %24, %25, %26, %27, %28, %29, %30, %31}, [%32];" \
        : "=r"((r)[0]),  "=r"((r)[1]),  "=r"((r)[2]),  "=r"((r)[3]),              \
          "=r"((r)[4]),  "=r"((r)[5]),  "=r"((r)[6]),  "=r"((r)[7]),              \
          "=r"((r)[8]),  "=r"((r)[9]),  "=r"((r)[10]), "=r"((r)[11]),             \
          "=r"((r)[12]), "=r"((r)[13]), "=r"((r)[14]), "=r"((r)[15]),             \
          "=r"((r)[16]), "=r"((r)[17]), "=r"((r)[18]), "=r"((r)[19]),             \
          "=r"((r)[20]), "=r"((r)[21]), "=r"((r)[22]), "=r"((r)[23]),             \
          "=r"((r)[24]), "=r"((r)[25]), "=r"((r)[26]), "=r"((r)[27]),             \
          "=r"((r)[28]), "=r"((r)[29]), "=r"((r)[30]), "=r"((r)[31])              \
        : "r"(a))
#endif

#define MBAR_INIT(a, c)   asm volatile("mbarrier.init.shared.b64 [%0], %1;" :: "r"(a), "r"((uint32_t)(c)) : "memory")
#define MBAR_WAIT(addr, ph) do {                                                 \
    uint32_t _d;                                                                 \
    asm volatile("{\n\t.reg .pred p;\n\t"                                        \
        "mbarrier.try_wait.parity.acquire.cta.shared::cta.b64 p, [%1], %2;\n\t"  \
        "selp.b32 %0, 1, 0, p;\n\t}" : "=r"(_d) : "r"(addr), "r"(ph) : "memory");\
    while (!_d)                                                                  \
        asm volatile("{\n\t.reg .pred p;\n\t"                                    \
            "mbarrier.try_wait.parity.acquire.cta.shared::cta.b64 p, [%1], %2, 0x989680;\n\t" \
            "selp.b32 %0, 1, 0, p;\n\t}" : "=r"(_d) : "r"(addr), "r"(ph) : "memory"); \
} while (0)
#define MBAR_WAIT_CL(addr, ph) do {                                              \
    uint32_t _d;                                                                 \
    asm volatile("{\n\t.reg .pred p;\n\t"                                        \
        "mbarrier.try_wait.parity.acquire.cluster.shared::cta.b64 p, [%1], %2;\n\t" \
        "selp.b32 %0, 1, 0, p;\n\t}" : "=r"(_d) : "r"(addr), "r"(ph) : "memory");\
    while (!_d)                                                                  \
        asm volatile("{\n\t.reg .pred p;\n\t"                                    \
            "mbarrier.try_wait.parity.acquire.cluster.shared::cta.b64 p, [%1], %2, 0x989680;\n\t" \
            "selp.b32 %0, 1, 0, p;\n\t}" : "=r"(_d) : "r"(addr), "r"(ph) : "memory"); \
} while (0)
#define ARRIVE_LEADER(addr)                                                      \
    asm volatile("{\n\t.reg .b32 ra;\n\t"                                        \
        "mapa.shared::cluster.u32 ra, %0, 0;\n\t"                                \
        "mbarrier.arrive.shared::cluster.b64 _, [ra];\n\t}"                      \
        :: "r"(addr) : "memory")
#define CLUSTER_SYNC() do {                                                      \
    asm volatile("barrier.cluster.arrive.aligned;" ::: "memory");                \
    asm volatile("barrier.cluster.wait.aligned;" ::: "memory");                  \
} while (0)

// ---- converts: row-major -> tiled [row/128][col/64][16KB SW128-swizzled] ------
__global__ void __launch_bounds__(256) cvt_i32_t(const int* __restrict__ s,
                                                 __half* __restrict__ d,
                                                 int cols, unsigned ngrp) {
    unsigned i = blockIdx.x * 256u + threadIdx.x;
    if (i >= ngrp) return;
    unsigned e = i * 8u;
    unsigned row = e / (unsigned)cols, col = e % (unsigned)cols;
    const int4* p = (const int4*)(s + (size_t)row * cols + col);
    int4 a = p[0], b = p[1];
    __half2 h0 = __floats2half2_rn((float)a.x, (float)a.y);
    __half2 h1 = __floats2half2_rn((float)a.z, (float)a.w);
    __half2 h2 = __floats2half2_rn((float)b.x, (float)b.y);
    __half2 h3 = __floats2half2_rn((float)b.z, (float)b.w);
    uint4 v = make_uint4(*(uint32_t*)&h0, *(uint32_t*)&h1, *(uint32_t*)&h2, *(uint32_t*)&h3);
    unsigned nkc = (unsigned)cols >> 6;
    size_t tile = (size_t)(row >> 7) * nkc + (col >> 6);
    uint32_t off = (row & 127u) * 128u + (col & 63u) * 2u;
    *(uint4*)((char*)d + tile * TILEB + SWZ(off)) = v;
}
__global__ void __launch_bounds__(256) cvt_f32_t(const float* __restrict__ s,
                                                 __half* __restrict__ d,
                                                 int cols, unsigned ngrp) {
    unsigned i = blockIdx.x * 256u + threadIdx.x;
    if (i >= ngrp) return;
    unsigned e = i * 8u;
    unsigned row = e / (unsigned)cols, col = e % (unsigned)cols;
    const float4* p = (const float4*)(s + (size_t)row * cols + col);
    float4 a = p[0], b = p[1];
    __half2 h0 = __floats2half2_rn(a.x, a.y);
    __half2 h1 = __floats2half2_rn(a.z, a.w);
    __half2 h2 = __floats2half2_rn(b.x, b.y);
    __half2 h3 = __floats2half2_rn(b.z, b.w);
    uint4 v = make_uint4(*(uint32_t*)&h0, *(uint32_t*)&h1, *(uint32_t*)&h2, *(uint32_t*)&h3);
    unsigned nkc = (unsigned)cols >> 6;
    size_t tile = (size_t)(row >> 7) * nkc + (col >> 6);
    uint32_t off = (row & 127u) * 128u + (col & 63u) * 2u;
    *(uint4*)((char*)d + tile * TILEB + SWZ(off)) = v;
}

// ---------------- GEMM1 (cg2, split W-ring/B-ring pipeline) --------------------
__global__ void __launch_bounds__(320, 1) __cluster_dims__(2, 1, 1)
ffn_gemm1(const float* __restrict__ gus) {
#if HAS_TCGEN05
    extern __shared__ char smem[];
    uint32_t sb = smem_u32(smem);
    const int tid = threadIdx.x, wid = tid >> 5, lid = tid & 31;
    uint32_t rank;
    asm("mov.u32 %0, %%cluster_ctarank;" : "=r"(rank));
    const int by = blockIdx.y, bz = blockIdx.z;
    const int t0 = by * 256, g0 = bz * 256;

    if (wid == 0) TCG_ALLOC2(sb, 512);
    if (tid == 0) {
#pragma unroll
        for (int s = 0; s < NSW1; s++) {
            MBAR_INIT(WFULL(sb, s), 256);
            MBAR_INIT(WEMPTY(sb, s), 1);
            MBAR_INIT(GFULL1(sb, s), 2);
        }
#pragma unroll
        for (int s = 0; s < NSB1; s++) {
            MBAR_INIT(BFULL(sb, s), 256);
            MBAR_INIT(BEMPTY(sb, s), 1);
        }
    }
    __syncthreads();
    uint32_t tb;
    asm volatile("ld.shared.b32 %0, [%1];" : "=r"(tb) : "r"(sb));
    CLUSTER_SYNC();

    const char* wb = (const char*)g_w1h;
    const char* xb = (const char*)g_xh;
    const size_t rbg = (size_t)(2 * bz + (int)rank);
    const size_t rbu = (size_t)(INTERC / 128 + 2 * bz + (int)rank);
    const size_t rbx = (size_t)(2 * by + (int)rank);

    if (tid < 256) {
        // producers: fill W ring then B ring each chunk
        for (int kc = 0; kc < NK1; kc++) {
            const int sw = kc % NSW1, sbi = kc % NSB1;
            if (kc >= NSW1)
                MBAR_WAIT(WEMPTY(sb, sw), (uint32_t)((kc / NSW1 + 1) & 1));
            const uint32_t wbase = sb + W1_OFF + (uint32_t)sw * 32768u;
            copy_tile(wbase,         wb + (rbg * NK1 + kc) * TILEB, tid);
            copy_tile(wbase + TILEB, wb + (rbu * NK1 + kc) * TILEB, tid);
            cpa_arrive(WFULL(sb, sw));
            if (kc >= NSB1)
                MBAR_WAIT(BEMPTY(sb, sbi), (uint32_t)((kc / NSB1 + 1) & 1));
            const uint32_t bbase = sb + B1_OFF + (uint32_t)sbi * 16384u;
            copy_tile(bbase, xb + (rbx * NK1 + kc) * TILEB, tid);
            cpa_arrive(BFULL(sb, sbi));
        }
    } else if (tid == 288) {
        // relay: both local fulls -> leader gfull
        for (int kc = 0; kc < NK1; kc++) {
            const int sw = kc % NSW1, sbi = kc % NSB1;
            MBAR_WAIT(WFULL(sb, sw), (uint32_t)((kc / NSW1) & 1));
            MBAR_WAIT(BFULL(sb, sbi), (uint32_t)((kc / NSB1) & 1));
            ARRIVE_LEADER(GFULL1(sb, sw));
        }
    } else if (tid == 256 && rank == 0) {
        // MMA issuer (leader)
        for (int kc = 0; kc < NK1; kc++) {
            const int sw = kc % NSW1, sbi = kc % NSB1;
            MBAR_WAIT_CL(GFULL1(sb, sw), (uint32_t)((kc / NSW1) & 1));
            asm volatile("fence.proxy.async.shared::cta;" ::: "memory");
            const uint32_t wbase = sb + W1_OFF + (uint32_t)sw * 32768u;
            const uint32_t bbase = sb + B1_OFF + (uint32_t)sbi * 16384u;
            uint64_t ad = make_desc(wbase);
            uint64_t au = make_desc(wbase + TILEB);
            uint64_t bd = make_desc(bbase);
#pragma unroll
            for (int ks = 0; ks < 4; ks++) {
                uint32_t en = (kc | ks) ? 1u : 0u;
                mma2_f16_ss(tb,        ad + ks * 2, bd + ks * 2, en);
                mma2_f16_ss(tb + 256u, au + ks * 2, bd + ks * 2, en);
            }
            TCG_COMMIT_MC(WEMPTY(sb, sw));
            TCG_COMMIT_MC(BEMPTY(sb, sbi));
        }
    }

    if (tid < 256) {
        MBAR_WAIT(WEMPTY(sb, (NK1 - 1) % NSW1), (uint32_t)(((NK1 - 1) / NSW1) & 1));
        TCG_FENCE_AFTER();
        const int wg = wid >> 2;
        const int o = g0 + (int)rank * 128 + ((wid & 3) << 5) + lid;
        const float sg = gus[o], su = gus[INTERC + o];
        char* hb = (char*)g_hid;
        const size_t tilebase = ((size_t)(2 * by + wg) * NK2 + (size_t)(o >> 6)) * TILEB;
        const uint32_t oc = (uint32_t)(o & 63) * 2u;
#pragma unroll
        for (int cc = 0; cc < 4; cc++) {
            const int cb = wg * 128 + cc * 32;
            uint32_t gr[32], ur[32];
            LDTM_X32(gr, tb + (uint32_t)cb);
            LDTM_X32(ur, tb + 256u + (uint32_t)cb);
            TCG_WAIT_LD();
#pragma unroll
            for (int j = 0; j < 32; j++) {
                float g = __uint_as_float(gr[j]) * sg;
                float u = __uint_as_float(ur[j]) * su;
                float h = g * u * 0.0625f / (1.0f + __expf(-g));
                uint32_t off = (uint32_t)(cc * 32 + j) * 128u + oc;
                *(__half*)(hb + tilebase + SWZ(off)) = __float2half_rn(h);
            }
        }
    }
    __syncthreads();
    CLUSTER_SYNC();
    if (wid == 0) { TCG_RELQ2(); TCG_DEALLOC2(tb, 512); }
    CLUSTER_SYNC();
#endif
}

// ---------------- GEMM2 (cg2, cp.async from tiled gmem) — unchanged R9 --------
__global__ void __launch_bounds__(320, 1) __cluster_dims__(2, 1, 1)
ffn_gemm2(const float* __restrict__ dsc, float* __restrict__ out) {
#if HAS_TCGEN05
    extern __shared__ char smem[];
    uint32_t sb = smem_u32(smem);
    const int tid = threadIdx.x, wid = tid >> 5, lid = tid & 31;
    uint32_t rank;
    asm("mov.u32 %0, %%cluster_ctarank;" : "=r"(rank));
    const int by = blockIdx.y, bz = blockIdx.z;
    const int t0 = by * 256, n0 = bz * 256;

    if (wid == 0) TCG_ALLOC2(sb, 256);
    if (tid == 0) {
#pragma unroll
        for (int s = 0; s < NSTG2; s++) {
            MBAR_INIT(LFULL(sb, s), 256);
            MBAR_INIT(EMPTYB(sb, s), 1);
            MBAR_INIT(GFULL(sb, s), 2);
        }
    }
    __syncthreads();
    uint32_t tb;
    asm volatile("ld.shared.b32 %0, [%1];" : "=r"(tb) : "r"(sb));
    CLUSTER_SYNC();

    const char* wb = (const char*)g_w2h;
    const char* hbs = (const char*)g_hid;
    const size_t rba = (size_t)(2 * bz + (int)rank);
    const size_t rbb = (size_t)(2 * by + (int)rank);

    if (tid < 256) {
        for (int kc = 0; kc < NK2; kc++) {
            const int s = kc % NSTG2, r = kc / NSTG2;
            if (kc >= NSTG2) MBAR_WAIT(EMPTYB(sb, s), (uint32_t)((r + 1) & 1));
            const uint32_t base = sb + 1024u + (uint32_t)s * STG2;
            copy_tile(base,         wb  + (rba * NK2 + kc) * TILEB, tid);
            copy_tile(base + TILEB, hbs + (rbb * NK2 + kc) * TILEB, tid);
            cpa_arrive(LFULL(sb, s));
        }
    } else if (tid == 288) {
        for (int kc = 0; kc < NK2; kc++) {
            const int s = kc % NSTG2, r = kc / NSTG2;
            MBAR_WAIT(LFULL(sb, s), (uint32_t)(r & 1));
            ARRIVE_LEADER(GFULL(sb, s));
        }
    } else if (tid == 256 && rank == 0) {
        for (int kc = 0; kc < NK2; kc++) {
            const int s = kc % NSTG2, r = kc / NSTG2;
            MBAR_WAIT_CL(GFULL(sb, s), (uint32_t)(r & 1));
            asm volatile("fence.proxy.async.shared::cta;" ::: "memory");
            const uint32_t base = sb + 1024u + (uint32_t)s * STG2;
            uint64_t ad = make_desc(base);
            uint64_t bd = make_desc(base + TILEB);
#pragma unroll
            for (int ks = 0; ks < 4; ks++)
                mma2_f16_ss(tb, ad + ks * 2, bd + ks * 2, (kc | ks) ? 1u : 0u);
            TCG_COMMIT_MC(EMPTYB(sb, s));
        }
    }

    if (tid < 256) {
        MBAR_WAIT(EMPTYB(sb, (NK2 - 1) % NSTG2), (uint32_t)(((NK2 - 1) / NSTG2) & 1));
        TCG_FENCE_AFTER();
        const int wg = wid >> 2;
        const int o = n0 + (int)rank * 128 + ((wid & 3) << 5) + lid;
        const float sc = dsc[o] * 16.0f;
#pragma unroll
        for (int cc = 0; cc < 4; cc++) {
            const int cb = wg * 128 + cc * 32;
            uint32_t dr[32];
            LDTM_X32(dr, tb + (uint32_t)cb);
            TCG_WAIT_LD();
#pragma unroll
            for (int j = 0; j < 32; j++)
                out[(size_t)(t0 + cb + j) * HID + o] = __uint_as_float(dr[j]) * sc;
        }
    }
    __syncthreads();
    CLUSTER_SYNC();
    if (wid == 0) { TCG_RELQ2(); TCG_DEALLOC2(tb, 256); }
    CLUSTER_SYNC();
#endif
}

extern "C" void kernel_launch(void* const* d_in, const int* in_sizes, int n_in,
                              void* d_out, int out_size) {
    const float* x  = (const float*)d_in[0];
    const int*  w1  = (const int*)d_in[1];
    const float* gus = (const float*)d_in[2];
    const int*  w2  = (const int*)d_in[3];
    const float* dsc = (const float*)d_in[4];
    float* out = (float*)d_out;

    void *p_xh, *p_w1, *p_w2;
    cudaGetSymbolAddress(&p_xh, g_xh);
    cudaGetSymbolAddress(&p_w1, g_w1h);
    cudaGetSymbolAddress(&p_w2, g_w2h);

    unsigned gx = (unsigned)((size_t)TOK * HID / 8);
    unsigned gw1 = (unsigned)((size_t)2 * INTERC * HID / 8);
    unsigned gw2 = (unsigned)((size_t)HID * INTERC / 8);
    cvt_f32_t<<<(gx + 255) / 256, 256>>>(x, (__half*)p_xh, HID, gx);
    cvt_i32_t<<<(gw1 + 255) / 256, 256>>>(w1, (__half*)p_w1, HID, gw1);
    cvt_i32_t<<<(gw2 + 255) / 256, 256>>>(w2, (__half*)p_w2, INTERC, gw2);

    cudaFuncSetAttribute(ffn_gemm1, cudaFuncAttributeMaxDynamicSharedMemorySize, SMEM1);
    cudaFuncSetAttribute(ffn_gemm2, cudaFuncAttributeMaxDynamicSharedMemorySize, SMEM2);

    dim3 g1(2, TOK / 256, INTERC / 256);
    ffn_gemm1<<<g1, 320, SMEM1>>>(gus);
    dim3 g2(2, TOK / 256, HID / 256);
    ffn_gemm2<<<g2, 320, SMEM2>>>(dsc, out);
}